// round 13
// baseline (speedup 1.0000x reference)
#include <cuda_runtime.h>
#include <cuda_fp16.h>
#include <cstdint>
#include <math.h>

// ============================================================================
// Shapes: B=4, T=1024, D=4096, N=32 heads, KH=8 kv heads, H=128, G=4
// ============================================================================

__device__ float  g_q   [4096UL * 4096];  // [t][n*128] q fp32 (dense)
__device__ float  g_gate[4096UL * 4096];  // [t][n*128] gate fp32 (dense)
__device__ float  g_k  [4096UL * 1024];
__device__ float  g_v  [4096UL * 1024];
__device__ __half g_xh  [4096UL * 4096];
__device__ __half g_wqh [4096UL * 8192];
__device__ __half g_wkh [4096UL * 1024];
__device__ __half g_wvh [4096UL * 1024];
__device__ __half g_woh [4096UL * 4096];
__device__ __half g_atth[4096UL * 4096];
__device__ __half g_qh  [131072UL * 128];
__device__ __half g_khT [32UL * 128 * 1024];
__device__ __half g_vh  [32UL * 1024 * 128];

struct HxStreams {
    cudaStream_t s1, s2, s3;
    cudaEvent_t e_root, e_x, e_qn, e_k, e_v, e_gate;
    HxStreams() {
        cudaStreamCreateWithFlags(&s1, cudaStreamNonBlocking);
        cudaStreamCreateWithFlags(&s2, cudaStreamNonBlocking);
        cudaStreamCreateWithFlags(&s3, cudaStreamNonBlocking);
        cudaEventCreateWithFlags(&e_root, cudaEventDisableTiming);
        cudaEventCreateWithFlags(&e_x,    cudaEventDisableTiming);
        cudaEventCreateWithFlags(&e_qn,   cudaEventDisableTiming);
        cudaEventCreateWithFlags(&e_k,    cudaEventDisableTiming);
        cudaEventCreateWithFlags(&e_v,    cudaEventDisableTiming);
        cudaEventCreateWithFlags(&e_gate, cudaEventDisableTiming);
    }
};
static HxStreams hxs;

__device__ __forceinline__ uint32_t smem_u32(const void* p) {
    uint32_t a;
    asm("{ .reg .u64 t; cvta.to.shared.u64 t, %1; cvt.u32.u64 %0, t; }"
        : "=r"(a) : "l"(p));
    return a;
}
__device__ __forceinline__ void cp16(uint32_t dst_smem, const void* src) {
    asm volatile("cp.async.cg.shared.global [%0], [%1], 16;"
                 :: "r"(dst_smem), "l"(src));
}
__device__ __forceinline__ void ldsm4(uint32_t* r, uint32_t addr) {
    asm volatile("ldmatrix.sync.aligned.m8n8.x4.shared.b16 {%0,%1,%2,%3}, [%4];"
                 : "=r"(r[0]), "=r"(r[1]), "=r"(r[2]), "=r"(r[3]) : "r"(addr));
}
__device__ __forceinline__ void ldsm4t(uint32_t* r, uint32_t addr) {
    asm volatile("ldmatrix.sync.aligned.m8n8.x4.trans.shared.b16 {%0,%1,%2,%3}, [%4];"
                 : "=r"(r[0]), "=r"(r[1]), "=r"(r[2]), "=r"(r[3]) : "r"(addr));
}
__device__ __forceinline__ void mma_f16(float* d, const uint32_t* a,
                                        uint32_t b0, uint32_t b1) {
    asm volatile(
        "mma.sync.aligned.m16n8k16.row.col.f32.f16.f16.f32 "
        "{%0,%1,%2,%3}, {%4,%5,%6,%7}, {%8,%9}, {%0,%1,%2,%3};"
        : "+f"(d[0]), "+f"(d[1]), "+f"(d[2]), "+f"(d[3])
        : "r"(a[0]), "r"(a[1]), "r"(a[2]), "r"(a[3]), "r"(b0), "r"(b1));
}
__device__ __forceinline__ uint32_t ex2_h2(float hi, float lo) {
    uint32_t h, d;
    asm("cvt.rn.f16x2.f32 %0, %1, %2;" : "=r"(h) : "f"(hi), "f"(lo));
    asm("ex2.approx.f16x2 %0, %1;" : "=r"(d) : "r"(h));
    return d;
}
__device__ __forceinline__ float ex2f(float x) {
    float r;
    asm("ex2.approx.f32 %0, %1;" : "=f"(r) : "f"(x));
    return r;
}

// ---------------------------------------------------------------------------
// fp16 mma.sync GEMM with strided-B (colmul), dense C. CTA 128x128, BK=64,
// 2 CTAs/SM, 3-stage cp.async, single sync/iter.
// ---------------------------------------------------------------------------
#define BM 128
#define BN 128
#define BK 64
#define STAGES 3
#define A_BYTES (128 * 128)
#define B_BYTES (64 * 256)
#define STAGE_BYTES (A_BYTES + B_BYTES)
#define GEMM_SMEM (STAGES * STAGE_BYTES)

__global__ __launch_bounds__(256, 2) void h16_gemm(
    const __half* __restrict__ A, const __half* __restrict__ B,
    float* __restrict__ C, int M, int N, int K, int ldb, int colmul)
{
    extern __shared__ char smem[];
    const uint32_t sbase = smem_u32(smem);
    const int tid  = threadIdx.x;
    const int wid  = tid >> 5;
    const int lane = tid & 31;
    const int g    = lane >> 2;
    const int c    = lane & 3;

    const int m0 = blockIdx.y * BM;
    const int n0 = blockIdx.x * BN;
    const int m_warp = (wid & 1) * 64;
    const int n_warp = (wid >> 1) * 32;
    const int NKT = K / BK;

    float acc[4][4][4];
#pragma unroll
    for (int i = 0; i < 4; i++)
#pragma unroll
        for (int j = 0; j < 4; j++)
#pragma unroll
            for (int r = 0; r < 4; r++) acc[i][j][r] = 0.0f;

    const int ar  = tid >> 1;
    const int ac  = tid & 1;
    const int brr = tid >> 2;
    const int bcg = tid & 3;

    const int lrow = (lane & 7) + ((lane >> 3) & 1) * 8;
    const int lkc  = lane >> 4;
    const int lxor = lane & 7;

    auto load_tile = [&](int kt) {
        const uint32_t sa = sbase + (kt % STAGES) * STAGE_BYTES;
        const uint32_t sb = sa + A_BYTES;
        const int k0 = kt * BK;
        const __half* ap = A + (size_t)(m0 + ar) * K + k0 + ac * 32;
#pragma unroll
        for (int j = 0; j < 4; j++) {
            int ch = ac * 4 + j;
            cp16(sa + ar * 128 + ((ch ^ (ar & 7)) * 16), ap + j * 8);
        }
        const __half* bp = B + (size_t)(k0 + brr) * ldb + n0 * colmul + bcg * 32;
#pragma unroll
        for (int j = 0; j < 4; j++) {
            int ch = bcg * 4 + j;
            cp16(sb + brr * 256 + ((ch ^ (brr & 7)) * 16), bp + j * 8);
        }
        asm volatile("cp.async.commit_group;" ::: "memory");
    };

#pragma unroll
    for (int s = 0; s < STAGES - 1; s++) load_tile(s);

    for (int kt = 0; kt < NKT; kt++) {
        if (kt + STAGES - 1 < NKT) {
            asm volatile("cp.async.wait_group %0;" :: "n"(STAGES - 2) : "memory");
        } else {
            asm volatile("cp.async.wait_group 0;" ::: "memory");
        }
        __syncthreads();
        if (kt + STAGES - 1 < NKT) load_tile(kt + STAGES - 1);

        const uint32_t sa = sbase + (kt % STAGES) * STAGE_BYTES;
        const uint32_t sb = sa + A_BYTES;

#pragma unroll
        for (int ks = 0; ks < BK / 16; ks++) {
            uint32_t a[4][4], b[2][4];
#pragma unroll
            for (int mt = 0; mt < 4; mt++) {
                int row = m_warp + mt * 16 + lrow;
                ldsm4(a[mt], sa + row * 128 + (((ks * 2 + lkc) ^ lxor) * 16));
            }
#pragma unroll
            for (int p = 0; p < 2; p++) {
                int krow = ks * 16 + lrow;
                int nc = (n_warp >> 3) + p * 2 + lkc;
                ldsm4t(b[p], sb + krow * 256 + ((nc ^ (krow & 7)) * 16));
            }
#pragma unroll
            for (int mt = 0; mt < 4; mt++)
#pragma unroll
                for (int p = 0; p < 2; p++) {
                    mma_f16(acc[mt][2 * p],     a[mt], b[p][0], b[p][1]);
                    mma_f16(acc[mt][2 * p + 1], a[mt], b[p][2], b[p][3]);
                }
        }
    }

#pragma unroll
    for (int mt = 0; mt < 4; mt++) {
        const int row = m0 + m_warp + mt * 16 + g;
#pragma unroll
        for (int nt = 0; nt < 4; nt++) {
            const int col = n0 + n_warp + nt * 8 + c * 2;
            *reinterpret_cast<float2*>(&C[(size_t)row * N + col]) =
                make_float2(acc[mt][nt][0], acc[mt][nt][1]);
            *reinterpret_cast<float2*>(&C[(size_t)(row + 8) * N + col]) =
                make_float2(acc[mt][nt][2], acc[mt][nt][3]);
        }
    }
}

// ---------------------------------------------------------------------------
// float -> half conversion, 64B per thread
// ---------------------------------------------------------------------------
__global__ void f2h_kernel(const float* __restrict__ in, __half* __restrict__ out)
{
    const int i = (blockIdx.x * blockDim.x + threadIdx.x) * 16;
#pragma unroll
    for (int j = 0; j < 4; j++) {
        float4 v = *reinterpret_cast<const float4*>(in + i + j * 4);
        *reinterpret_cast<__half2*>(out + i + j * 4)     = __floats2half2_rn(v.x, v.y);
        *reinterpret_cast<__half2*>(out + i + j * 4 + 2) = __floats2half2_rn(v.z, v.w);
    }
}

// ---------------------------------------------------------------------------
// Gate apply: atth *= sigmoid(gate)
// ---------------------------------------------------------------------------
__global__ void gate_apply_kernel(__half* __restrict__ o,
                                  const float* __restrict__ gate)
{
    const int i = (blockIdx.x * blockDim.x + threadIdx.x) * 8;
#pragma unroll
    for (int j = 0; j < 2; j++) {
        float4 gv = *reinterpret_cast<const float4*>(gate + i + j * 4);
        __half2 h0 = *reinterpret_cast<__half2*>(o + i + j * 4);
        __half2 h1 = *reinterpret_cast<__half2*>(o + i + j * 4 + 2);
        float2 f0 = __half22float2(h0);
        float2 f1 = __half22float2(h1);
        f0.x *= 1.0f / (1.0f + __expf(-gv.x));
        f0.y *= 1.0f / (1.0f + __expf(-gv.y));
        f1.x *= 1.0f / (1.0f + __expf(-gv.z));
        f1.y *= 1.0f / (1.0f + __expf(-gv.w));
        *reinterpret_cast<__half2*>(o + i + j * 4)     = __floats2half2_rn(f0.x, f0.y);
        *reinterpret_cast<__half2*>(o + i + j * 4 + 2) = __floats2half2_rn(f1.x, f1.y);
    }
}

// ---------------------------------------------------------------------------
// RMSNorm + RoPE core
// ---------------------------------------------------------------------------
__device__ __forceinline__ float4 norm_rope_row(
    float4 x, const float* __restrict__ w, int lane, float pos)
{
    float ss = x.x*x.x + x.y*x.y + x.z*x.z + x.w*x.w;
#pragma unroll
    for (int o = 16; o; o >>= 1) ss += __shfl_xor_sync(0xffffffffu, ss, o);
    float r = rsqrtf(ss * (1.0f / 128.0f) + 1e-6f);
    float4 wv = *reinterpret_cast<const float4*>(w + 4 * lane);
    x.x *= r * (1.0f + wv.x);
    x.y *= r * (1.0f + wv.y);
    x.z *= r * (1.0f + wv.z);
    x.w *= r * (1.0f + wv.w);

    const int h0 = lane * 4;
    const int partner = (lane < 10) ? lane + 10 : ((lane < 20) ? lane - 10 : lane);
    float px = __shfl_sync(0xffffffffu, x.x, partner);
    float py = __shfl_sync(0xffffffffu, x.y, partner);
    float pz = __shfl_sync(0xffffffffu, x.z, partner);
    float pw = __shfl_sync(0xffffffffu, x.w, partner);

    if (h0 < 80) {
        const bool first = (h0 < 40);
        const float base_i = (float)(first ? h0 : h0 - 40);
        const float sgn = first ? -1.0f : 1.0f;
        float vals[4] = {x.x, x.y, x.z, x.w};
        float ps[4]   = {px, py, pz, pw};
        const float c2 = 0.49828921423310436f;    // log2(1e6)/40
#pragma unroll
        for (int j = 0; j < 4; j++) {
            float ts = exp2f((base_i + (float)j) * c2);
            float s, cc;
            sincosf(pos / ts, &s, &cc);
            vals[j] = vals[j] * cc + sgn * ps[j] * s;
        }
        x.x = vals[0]; x.y = vals[1]; x.z = vals[2]; x.w = vals[3];
    }
    return x;
}

__global__ void norm_rope_k_kernel(
    float* __restrict__ buf, const int* __restrict__ positions,
    const float* __restrict__ w)
{
    const int gw   = (blockIdx.x * blockDim.x + threadIdx.x) >> 5;
    const int lane = threadIdx.x & 31;
    const int kh = gw & 7;
    const int m  = gw >> 3;
    float* row = buf + (size_t)m * 1024 + kh * 128;
    float4 x = *reinterpret_cast<const float4*>(row + 4 * lane);
    x = norm_rope_row(x, w, lane, (float)positions[m]);
    *reinterpret_cast<float4*>(row + 4 * lane) = x;
}

__global__ void norm_rope_q_kernel(
    const float* __restrict__ q, const int* __restrict__ positions,
    const float* __restrict__ w, __half* __restrict__ qh)
{
    const int gw   = (blockIdx.x * blockDim.x + threadIdx.x) >> 5;
    const int lane = threadIdx.x & 31;
    const int n = gw & 31;
    const int m = gw >> 5;
    const float* row = q + (size_t)m * 4096 + n * 128;
    float4 x = *reinterpret_cast<const float4*>(row + 4 * lane);
    x = norm_rope_row(x, w, lane, (float)positions[m]);
    const float scale = 0.08838834764831845f * 1.4426950408889634f;
    const int b = m >> 10, t = m & 1023;
    __half2* o = reinterpret_cast<__half2*>(
        qh + ((size_t)((b * 32 + n) * 1024 + t)) * 128 + 4 * lane);
    o[0] = __floats2half2_rn(x.x * scale, x.y * scale);
    o[1] = __floats2half2_rn(x.z * scale, x.w * scale);
}

// ---------------------------------------------------------------------------
// K transpose -> half [h][s]
// ---------------------------------------------------------------------------
__global__ void transpose_k_half(const float* __restrict__ in,
                                 __half* __restrict__ out)
{
    __shared__ float tbuf[32][33];
    const int bk = blockIdx.y;
    const int b = bk >> 3, kh = bk & 7;
    const int th = (blockIdx.x & 3) * 32;
    const int ts = (blockIdx.x >> 2) * 32;
    const int x = threadIdx.x, y = threadIdx.y;
#pragma unroll
    for (int j = 0; j < 32; j += 8)
        tbuf[y + j][x] = in[(size_t)(b * 1024 + ts + y + j) * 1024 + kh * 128 + th + x];
    __syncthreads();
#pragma unroll
    for (int j = 0; j < 32; j += 8)
        out[(size_t)(bk * 128 + th + y + j) * 1024 + ts + x] =
            __float2half_rn(tbuf[x][y + j]);
}

// ---------------------------------------------------------------------------
// V reorder+convert -> half head-major
// ---------------------------------------------------------------------------
__global__ void v_reorder_half(const float* __restrict__ in,
                               __half* __restrict__ out)
{
    const int idx = (blockIdx.x * blockDim.x + threadIdx.x) * 4;
    const int h4 = idx & 1023;
    const int bs = idx >> 10;
    const int kh = h4 >> 7, h = h4 & 127;
    const int b = bs >> 10, s = bs & 1023;
    float4 v = *reinterpret_cast<const float4*>(in + idx);
    __half2* o = reinterpret_cast<__half2*>(
        out + ((size_t)((b * 8 + kh) * 1024 + s)) * 128 + h);
    o[0] = __floats2half2_rn(v.x, v.y);
    o[1] = __floats2half2_rn(v.z, v.w);
}

// ---------------------------------------------------------------------------
// Tensor-core flash attention (no gating). LPT order.
// ---------------------------------------------------------------------------
#define ATT_SMEM 81920
#define ONES_H2 0x3C003C00u

__global__ __launch_bounds__(128, 2) void attn_tc_kernel(
    const __half* __restrict__ qh, const __half* __restrict__ khT,
    const __half* __restrict__ vh, __half* __restrict__ outh)
{
    extern __shared__ char smem[];
    const uint32_t sbase = smem_u32(smem);
    const int tid  = threadIdx.x;
    const int wid  = tid >> 5;
    const int lane = tid & 31;
    const int g    = lane >> 2;
    const int c    = lane & 3;
    const int lrow = (lane & 7) + ((lane >> 3) & 1) * 8;
    const int lkc  = lane >> 4;

    const int qt = 15 - blockIdx.x;
    const int n  = blockIdx.y;
    const int b  = blockIdx.z;
    const int kh = n >> 2;
    const int bkh = b * 8 + kh;
    const int NT = qt + 1;

    auto load_q = [&]() {
        const __half* qp = qh + ((size_t)((b * 32 + n) * 1024 + qt * 64)) * 128;
#pragma unroll
        for (int j = 0; j < 8; j++) {
            int idx = tid + j * 128;
            int r = idx >> 4, ch = idx & 15;
            cp16(sbase + r * 256 + ((ch ^ (r & 7)) * 16), qp + r * 128 + ch * 8);
        }
    };
    auto load_kv = [&](int kt) {
        const uint32_t skb = sbase + 16384 + (kt & 1) * 32768;
        const uint32_t svb = skb + 16384;
        const __half* kp = khT + ((size_t)bkh * 128) * 1024 + kt * 64;
#pragma unroll
        for (int j = 0; j < 8; j++) {
            int idx = tid + j * 128;
            int r = idx >> 3, ch = idx & 7;
            cp16(skb + r * 128 + ((ch ^ (r & 7)) * 16), kp + (size_t)r * 1024 + ch * 8);
        }
        const __half* vp = vh + ((size_t)(bkh * 1024 + kt * 64)) * 128;
#pragma unroll
        for (int j = 0; j < 8; j++) {
            int idx = tid + j * 128;
            int r = idx >> 4, ch = idx & 15;
            cp16(svb + r * 256 + ((ch ^ (r & 7)) * 16), vp + r * 128 + ch * 8);
        }
        asm volatile("cp.async.commit_group;" ::: "memory");
    };

    load_q();
    load_kv(0);
    if (NT > 1) load_kv(1);

    uint32_t qa[8][4];
    float o[16][4];
#pragma unroll
    for (int i = 0; i < 16; i++)
#pragma unroll
        for (int r = 0; r < 4; r++) o[i][r] = 0.0f;
    float ol[4] = {0.f, 0.f, 0.f, 0.f};
    float m0 = -3.4e38f, m1 = -3.4e38f;

    for (int kt = 0; kt < NT; kt++) {
        if (kt + 1 < NT) {
            asm volatile("cp.async.wait_group 1;" ::: "memory");
        } else {
            asm volatile("cp.async.wait_group 0;" ::: "memory");
        }
        __syncthreads();

        if (kt == 0) {
#pragma unroll
            for (int ks = 0; ks < 8; ks++) {
                int row = wid * 16 + lrow;
                ldsm4(qa[ks], sbase + row * 256 + (((ks * 2 + lkc) ^ (lrow & 7)) * 16));
            }
        }

        const uint32_t skb = sbase + 16384 + (kt & 1) * 32768;
        const uint32_t svb = skb + 16384;

        float sc[8][4];
#pragma unroll
        for (int i = 0; i < 8; i++)
#pragma unroll
            for (int r = 0; r < 4; r++) sc[i][r] = 0.0f;

#pragma unroll
        for (int ks = 0; ks < 8; ks++) {
            uint32_t bk[4][4];
            int krow = ks * 16 + lrow;
#pragma unroll
            for (int p = 0; p < 4; p++) {
                int nc = p * 2 + lkc;
                ldsm4t(bk[p], skb + krow * 128 + ((nc ^ (krow & 7)) * 16));
            }
#pragma unroll
            for (int p = 0; p < 4; p++) {
                mma_f16(sc[2 * p],     qa[ks], bk[p][0], bk[p][1]);
                mma_f16(sc[2 * p + 1], qa[ks], bk[p][2], bk[p][3]);
            }
        }

        const int r0 = wid * 16 + g;
        if (kt == qt) {
#pragma unroll
            for (int j = 0; j < 8; j++) {
                int k0 = j * 8 + 2 * c;
                if (k0     > r0)     sc[j][0] = -1e30f;
                if (k0 + 1 > r0)     sc[j][1] = -1e30f;
                if (k0     > r0 + 8) sc[j][2] = -1e30f;
                if (k0 + 1 > r0 + 8) sc[j][3] = -1e30f;
            }
        }

        float mx0 = -3.4e38f, mx1 = -3.4e38f;
#pragma unroll
        for (int j = 0; j < 8; j++) {
            mx0 = fmaxf(mx0, fmaxf(sc[j][0], sc[j][1]));
            mx1 = fmaxf(mx1, fmaxf(sc[j][2], sc[j][3]));
        }
        mx0 = fmaxf(mx0, __shfl_xor_sync(0xffffffffu, mx0, 1));
        mx0 = fmaxf(mx0, __shfl_xor_sync(0xffffffffu, mx0, 2));
        mx1 = fmaxf(mx1, __shfl_xor_sync(0xffffffffu, mx1, 1));
        mx1 = fmaxf(mx1, __shfl_xor_sync(0xffffffffu, mx1, 2));

        float mn0 = fmaxf(m0, mx0), mn1 = fmaxf(m1, mx1);
        float a0 = ex2f(m0 - mn0), a1 = ex2f(m1 - mn1);
        m0 = mn0; m1 = mn1;

        uint32_t p_lo[8], p_hi[8];
#pragma unroll
        for (int j = 0; j < 8; j++) {
            p_lo[j] = ex2_h2(sc[j][1] - mn0, sc[j][0] - mn0);
            p_hi[j] = ex2_h2(sc[j][3] - mn1, sc[j][2] - mn1);
        }

        ol[0] *= a0; ol[1] *= a0; ol[2] *= a1; ol[3] *= a1;
#pragma unroll
        for (int i = 0; i < 16; i++) {
            o[i][0] *= a0; o[i][1] *= a0;
            o[i][2] *= a1; o[i][3] *= a1;
        }

#pragma unroll
        for (int j2 = 0; j2 < 4; j2++) {
            uint32_t pa[4] = { p_lo[2 * j2], p_hi[2 * j2],
                               p_lo[2 * j2 + 1], p_hi[2 * j2 + 1] };
            mma_f16(ol, pa, ONES_H2, ONES_H2);
            int krow = j2 * 16 + lrow;
#pragma unroll
            for (int p = 0; p < 8; p++) {
                uint32_t bv[4];
                int nc = p * 2 + lkc;
                ldsm4t(bv, svb + krow * 256 + ((nc ^ (krow & 7)) * 16));
                mma_f16(o[2 * p],     pa, bv[0], bv[1]);
                mma_f16(o[2 * p + 1], pa, bv[2], bv[3]);
            }
        }

        __syncthreads();
        if (kt + 2 < NT) load_kv(kt + 2);
    }

    const float inv0 = 1.0f / ol[0], inv1 = 1.0f / ol[2];
    const int tq0 = qt * 64 + wid * 16 + g;
    const int tq1 = tq0 + 8;
    __half* out0 = outh + (size_t)(b * 1024 + tq0) * 4096 + n * 128;
    __half* out1 = outh + (size_t)(b * 1024 + tq1) * 4096 + n * 128;
#pragma unroll
    for (int p = 0; p < 16; p++) {
        int col = p * 8 + 2 * c;
        *reinterpret_cast<__half2*>(out0 + col) =
            __floats2half2_rn(o[p][0] * inv0, o[p][1] * inv0);
        *reinterpret_cast<__half2*>(out1 + col) =
            __floats2half2_rn(o[p][2] * inv1, o[p][3] * inv1);
    }
}

// ---------------------------------------------------------------------------
// Launcher: gate-GEMM released only after norm_rope_q (e_qn), so it overlaps
// norm+attention instead of contending with the q-GEMM.
// ---------------------------------------------------------------------------
extern "C" void kernel_launch(void* const* d_in, const int* in_sizes, int n_in,
                              void* d_out, int out_size)
{
    const float* x   = (const float*)d_in[0];
    const int*   pos = (const int*)  d_in[1];
    const float* wq  = (const float*)d_in[2];
    const float* wk  = (const float*)d_in[3];
    const float* wv  = (const float*)d_in[4];
    const float* wo  = (const float*)d_in[5];
    const float* qw  = (const float*)d_in[6];
    const float* kw  = (const float*)d_in[7];
    float* out = (float*)d_out;

    float  *qb, *gateb, *kb, *vb;
    __half *xh, *wqh, *wkh, *wvh, *woh, *atth, *qh, *khT, *vh;
    cudaGetSymbolAddress((void**)&qb,    g_q);
    cudaGetSymbolAddress((void**)&gateb, g_gate);
    cudaGetSymbolAddress((void**)&kb,    g_k);
    cudaGetSymbolAddress((void**)&vb,    g_v);
    cudaGetSymbolAddress((void**)&xh,    g_xh);
    cudaGetSymbolAddress((void**)&wqh,   g_wqh);
    cudaGetSymbolAddress((void**)&wkh,   g_wkh);
    cudaGetSymbolAddress((void**)&wvh,   g_wvh);
    cudaGetSymbolAddress((void**)&woh,   g_woh);
    cudaGetSymbolAddress((void**)&atth,  g_atth);
    cudaGetSymbolAddress((void**)&qh,    g_qh);
    cudaGetSymbolAddress((void**)&khT,   g_khT);
    cudaGetSymbolAddress((void**)&vh,    g_vh);

    static bool attr_set = false;
    if (!attr_set) {
        cudaFuncSetAttribute(h16_gemm, cudaFuncAttributeMaxDynamicSharedMemorySize,
                             GEMM_SMEM);
        cudaFuncSetAttribute(attn_tc_kernel,
                             cudaFuncAttributeMaxDynamicSharedMemorySize, ATT_SMEM);
        attr_set = true;
    }

    cudaStream_t s0 = 0;

    cudaEventRecord(hxs.e_root, s0);
    cudaStreamWaitEvent(hxs.s1, hxs.e_root, 0);
    cudaStreamWaitEvent(hxs.s2, hxs.e_root, 0);
    cudaStreamWaitEvent(hxs.s3, hxs.e_root, 0);

    // s3: wo conversion first (needed only at the very end)
    f2h_kernel<<<(4096UL * 4096) / 4096, 256, 0, hxs.s3>>>(wo, woh);

    // main: x conversion -> fork
    f2h_kernel<<<(4096UL * 4096) / 4096, 256, 0, s0>>>(x, xh);
    cudaEventRecord(hxs.e_x, s0);
    cudaStreamWaitEvent(hxs.s1, hxs.e_x, 0);
    cudaStreamWaitEvent(hxs.s2, hxs.e_x, 0);

    // s1: K chain
    f2h_kernel<<<(4096UL * 1024) / 4096, 256, 0, hxs.s1>>>(wk, wkh);
    h16_gemm<<<dim3(8, 32), 256, GEMM_SMEM, hxs.s1>>>(
        xh, wkh, kb, 4096, 1024, 4096, 1024, 1);
    norm_rope_k_kernel<<<(4096 * 8) / 8, 256, 0, hxs.s1>>>(kb, pos, kw);
    transpose_k_half<<<dim3(128, 32), dim3(32, 8), 0, hxs.s1>>>(kb, khT);
    cudaEventRecord(hxs.e_k, hxs.s1);

    // s2: V chain
    f2h_kernel<<<(4096UL * 1024) / 4096, 256, 0, hxs.s2>>>(wv, wvh);
    h16_gemm<<<dim3(8, 32), 256, GEMM_SMEM, hxs.s2>>>(
        xh, wvh, vb, 4096, 1024, 4096, 1024, 1);
    v_reorder_half<<<(4096UL * 1024) / 1024, 256, 0, hxs.s2>>>(vb, vh);
    cudaEventRecord(hxs.e_v, hxs.s2);

    // main: wq conversion, q-GEMM (strided: head n -> wq cols n*256..+127)
    f2h_kernel<<<(4096UL * 8192) / 4096, 256, 0, s0>>>(wq, wqh);
    h16_gemm<<<dim3(32, 32), 256, GEMM_SMEM, s0>>>(
        xh, wqh, qb, 4096, 4096, 4096, 8192, 2);
    norm_rope_q_kernel<<<(4096 * 32) / 8, 256, 0, s0>>>(qb, pos, qw, qh);
    cudaEventRecord(hxs.e_qn, s0);

    // s3: gate-GEMM released only now -> overlaps attention, not the q-GEMM
    cudaStreamWaitEvent(hxs.s3, hxs.e_qn, 0);
    h16_gemm<<<dim3(32, 32), 256, GEMM_SMEM, hxs.s3>>>(
        xh, wqh + 128, gateb, 4096, 4096, 4096, 8192, 2);
    cudaEventRecord(hxs.e_gate, hxs.s3);

    // main: join K/V, attention (ungated output)
    cudaStreamWaitEvent(s0, hxs.e_k, 0);
    cudaStreamWaitEvent(s0, hxs.e_v, 0);
    attn_tc_kernel<<<dim3(16, 32, 4), 128, ATT_SMEM, s0>>>(qh, khT, vh, atth);

    // join gate-GEMM (also orders woh), apply gate, out-projection
    cudaStreamWaitEvent(s0, hxs.e_gate, 0);
    gate_apply_kernel<<<(4096UL * 4096) / 2048, 256, 0, s0>>>(atth, gateb);
    h16_gemm<<<dim3(32, 32), 256, GEMM_SMEM, s0>>>(
        atth, woh, out, 4096, 4096, 4096, 4096, 1);
}

// round 14
// speedup vs baseline: 1.0387x; 1.0387x over previous
#include <cuda_runtime.h>
#include <cuda_fp16.h>
#include <cstdint>
#include <math.h>

// ============================================================================
// Shapes: B=4, T=1024, D=4096, N=32 heads, KH=8 kv heads, H=128, G=4
// ============================================================================

__device__ float  g_q   [4096UL * 4096];  // [t][n*128] q fp32 (dense)
__device__ float  g_gate[4096UL * 4096];  // [t][n*128] gate fp32 (dense)
__device__ float  g_k  [4096UL * 1024];
__device__ float  g_v  [4096UL * 1024];
__device__ __half g_xh  [4096UL * 4096];
__device__ __half g_wqh [4096UL * 8192];
__device__ __half g_wkh [4096UL * 1024];
__device__ __half g_wvh [4096UL * 1024];
__device__ __half g_woh [4096UL * 4096];
__device__ __half g_atth[4096UL * 4096];
__device__ __half g_qh  [131072UL * 128];
__device__ __half g_khT [32UL * 128 * 1024];
__device__ __half g_vh  [32UL * 1024 * 128];

struct HxStreams {
    cudaStream_t s1, s2, s3;
    cudaEvent_t e_root, e_x, e_wq, e_k, e_v, e_gate;
    HxStreams() {
        cudaStreamCreateWithFlags(&s1, cudaStreamNonBlocking);
        cudaStreamCreateWithFlags(&s2, cudaStreamNonBlocking);
        cudaStreamCreateWithFlags(&s3, cudaStreamNonBlocking);
        cudaEventCreateWithFlags(&e_root, cudaEventDisableTiming);
        cudaEventCreateWithFlags(&e_x,    cudaEventDisableTiming);
        cudaEventCreateWithFlags(&e_wq,   cudaEventDisableTiming);
        cudaEventCreateWithFlags(&e_k,    cudaEventDisableTiming);
        cudaEventCreateWithFlags(&e_v,    cudaEventDisableTiming);
        cudaEventCreateWithFlags(&e_gate, cudaEventDisableTiming);
    }
};
static HxStreams hxs;

__device__ __forceinline__ uint32_t smem_u32(const void* p) {
    uint32_t a;
    asm("{ .reg .u64 t; cvta.to.shared.u64 t, %1; cvt.u32.u64 %0, t; }"
        : "=r"(a) : "l"(p));
    return a;
}
__device__ __forceinline__ void cp16(uint32_t dst_smem, const void* src) {
    asm volatile("cp.async.cg.shared.global [%0], [%1], 16;"
                 :: "r"(dst_smem), "l"(src));
}
__device__ __forceinline__ void ldsm4(uint32_t* r, uint32_t addr) {
    asm volatile("ldmatrix.sync.aligned.m8n8.x4.shared.b16 {%0,%1,%2,%3}, [%4];"
                 : "=r"(r[0]), "=r"(r[1]), "=r"(r[2]), "=r"(r[3]) : "r"(addr));
}
__device__ __forceinline__ void ldsm4t(uint32_t* r, uint32_t addr) {
    asm volatile("ldmatrix.sync.aligned.m8n8.x4.trans.shared.b16 {%0,%1,%2,%3}, [%4];"
                 : "=r"(r[0]), "=r"(r[1]), "=r"(r[2]), "=r"(r[3]) : "r"(addr));
}
__device__ __forceinline__ void mma_f16(float* d, const uint32_t* a,
                                        uint32_t b0, uint32_t b1) {
    asm volatile(
        "mma.sync.aligned.m16n8k16.row.col.f32.f16.f16.f32 "
        "{%0,%1,%2,%3}, {%4,%5,%6,%7}, {%8,%9}, {%0,%1,%2,%3};"
        : "+f"(d[0]), "+f"(d[1]), "+f"(d[2]), "+f"(d[3])
        : "r"(a[0]), "r"(a[1]), "r"(a[2]), "r"(a[3]), "r"(b0), "r"(b1));
}
__device__ __forceinline__ uint32_t ex2_h2(float hi, float lo) {
    uint32_t h, d;
    asm("cvt.rn.f16x2.f32 %0, %1, %2;" : "=r"(h) : "f"(hi), "f"(lo));
    asm("ex2.approx.f16x2 %0, %1;" : "=r"(d) : "r"(h));
    return d;
}
__device__ __forceinline__ float ex2f(float x) {
    float r;
    asm("ex2.approx.f32 %0, %1;" : "=f"(r) : "f"(x));
    return r;
}

// ---------------------------------------------------------------------------
// fp16 mma.sync GEMM with strided-B (colmul), dense C. CTA 128x128, BK=64,
// 2 CTAs/SM, 3-stage cp.async, single sync/iter.
// ---------------------------------------------------------------------------
#define BM 128
#define BN 128
#define BK 64
#define STAGES 3
#define A_BYTES (128 * 128)
#define B_BYTES (64 * 256)
#define STAGE_BYTES (A_BYTES + B_BYTES)
#define GEMM_SMEM (STAGES * STAGE_BYTES)

__global__ __launch_bounds__(256, 2) void h16_gemm(
    const __half* __restrict__ A, const __half* __restrict__ B,
    float* __restrict__ C, int M, int N, int K, int ldb, int colmul)
{
    extern __shared__ char smem[];
    const uint32_t sbase = smem_u32(smem);
    const int tid  = threadIdx.x;
    const int wid  = tid >> 5;
    const int lane = tid & 31;
    const int g    = lane >> 2;
    const int c    = lane & 3;

    const int m0 = blockIdx.y * BM;
    const int n0 = blockIdx.x * BN;
    const int m_warp = (wid & 1) * 64;
    const int n_warp = (wid >> 1) * 32;
    const int NKT = K / BK;

    float acc[4][4][4];
#pragma unroll
    for (int i = 0; i < 4; i++)
#pragma unroll
        for (int j = 0; j < 4; j++)
#pragma unroll
            for (int r = 0; r < 4; r++) acc[i][j][r] = 0.0f;

    const int ar  = tid >> 1;
    const int ac  = tid & 1;
    const int brr = tid >> 2;
    const int bcg = tid & 3;

    const int lrow = (lane & 7) + ((lane >> 3) & 1) * 8;
    const int lkc  = lane >> 4;
    const int lxor = lane & 7;

    auto load_tile = [&](int kt) {
        const uint32_t sa = sbase + (kt % STAGES) * STAGE_BYTES;
        const uint32_t sb = sa + A_BYTES;
        const int k0 = kt * BK;
        const __half* ap = A + (size_t)(m0 + ar) * K + k0 + ac * 32;
#pragma unroll
        for (int j = 0; j < 4; j++) {
            int ch = ac * 4 + j;
            cp16(sa + ar * 128 + ((ch ^ (ar & 7)) * 16), ap + j * 8);
        }
        const __half* bp = B + (size_t)(k0 + brr) * ldb + n0 * colmul + bcg * 32;
#pragma unroll
        for (int j = 0; j < 4; j++) {
            int ch = bcg * 4 + j;
            cp16(sb + brr * 256 + ((ch ^ (brr & 7)) * 16), bp + j * 8);
        }
        asm volatile("cp.async.commit_group;" ::: "memory");
    };

#pragma unroll
    for (int s = 0; s < STAGES - 1; s++) load_tile(s);

    for (int kt = 0; kt < NKT; kt++) {
        if (kt + STAGES - 1 < NKT) {
            asm volatile("cp.async.wait_group %0;" :: "n"(STAGES - 2) : "memory");
        } else {
            asm volatile("cp.async.wait_group 0;" ::: "memory");
        }
        __syncthreads();
        if (kt + STAGES - 1 < NKT) load_tile(kt + STAGES - 1);

        const uint32_t sa = sbase + (kt % STAGES) * STAGE_BYTES;
        const uint32_t sb = sa + A_BYTES;

#pragma unroll
        for (int ks = 0; ks < BK / 16; ks++) {
            uint32_t a[4][4], b[2][4];
#pragma unroll
            for (int mt = 0; mt < 4; mt++) {
                int row = m_warp + mt * 16 + lrow;
                ldsm4(a[mt], sa + row * 128 + (((ks * 2 + lkc) ^ lxor) * 16));
            }
#pragma unroll
            for (int p = 0; p < 2; p++) {
                int krow = ks * 16 + lrow;
                int nc = (n_warp >> 3) + p * 2 + lkc;
                ldsm4t(b[p], sb + krow * 256 + ((nc ^ (krow & 7)) * 16));
            }
#pragma unroll
            for (int mt = 0; mt < 4; mt++)
#pragma unroll
                for (int p = 0; p < 2; p++) {
                    mma_f16(acc[mt][2 * p],     a[mt], b[p][0], b[p][1]);
                    mma_f16(acc[mt][2 * p + 1], a[mt], b[p][2], b[p][3]);
                }
        }
    }

#pragma unroll
    for (int mt = 0; mt < 4; mt++) {
        const int row = m0 + m_warp + mt * 16 + g;
#pragma unroll
        for (int nt = 0; nt < 4; nt++) {
            const int col = n0 + n_warp + nt * 8 + c * 2;
            *reinterpret_cast<float2*>(&C[(size_t)row * N + col]) =
                make_float2(acc[mt][nt][0], acc[mt][nt][1]);
            *reinterpret_cast<float2*>(&C[(size_t)(row + 8) * N + col]) =
                make_float2(acc[mt][nt][2], acc[mt][nt][3]);
        }
    }
}

// ---------------------------------------------------------------------------
// float -> half conversion, 64B per thread
// ---------------------------------------------------------------------------
__global__ void f2h_kernel(const float* __restrict__ in, __half* __restrict__ out)
{
    const int i = (blockIdx.x * blockDim.x + threadIdx.x) * 16;
#pragma unroll
    for (int j = 0; j < 4; j++) {
        float4 v = *reinterpret_cast<const float4*>(in + i + j * 4);
        *reinterpret_cast<__half2*>(out + i + j * 4)     = __floats2half2_rn(v.x, v.y);
        *reinterpret_cast<__half2*>(out + i + j * 4 + 2) = __floats2half2_rn(v.z, v.w);
    }
}

// ---------------------------------------------------------------------------
// Gate apply: atth *= sigmoid(gate)
// ---------------------------------------------------------------------------
__global__ void gate_apply_kernel(__half* __restrict__ o,
                                  const float* __restrict__ gate)
{
    const int i = (blockIdx.x * blockDim.x + threadIdx.x) * 8;
#pragma unroll
    for (int j = 0; j < 2; j++) {
        float4 gv = *reinterpret_cast<const float4*>(gate + i + j * 4);
        __half2 h0 = *reinterpret_cast<__half2*>(o + i + j * 4);
        __half2 h1 = *reinterpret_cast<__half2*>(o + i + j * 4 + 2);
        float2 f0 = __half22float2(h0);
        float2 f1 = __half22float2(h1);
        f0.x *= 1.0f / (1.0f + __expf(-gv.x));
        f0.y *= 1.0f / (1.0f + __expf(-gv.y));
        f1.x *= 1.0f / (1.0f + __expf(-gv.z));
        f1.y *= 1.0f / (1.0f + __expf(-gv.w));
        *reinterpret_cast<__half2*>(o + i + j * 4)     = __floats2half2_rn(f0.x, f0.y);
        *reinterpret_cast<__half2*>(o + i + j * 4 + 2) = __floats2half2_rn(f1.x, f1.y);
    }
}

// ---------------------------------------------------------------------------
// RMSNorm + RoPE core
// ---------------------------------------------------------------------------
__device__ __forceinline__ float4 norm_rope_row(
    float4 x, const float* __restrict__ w, int lane, float pos)
{
    float ss = x.x*x.x + x.y*x.y + x.z*x.z + x.w*x.w;
#pragma unroll
    for (int o = 16; o; o >>= 1) ss += __shfl_xor_sync(0xffffffffu, ss, o);
    float r = rsqrtf(ss * (1.0f / 128.0f) + 1e-6f);
    float4 wv = *reinterpret_cast<const float4*>(w + 4 * lane);
    x.x *= r * (1.0f + wv.x);
    x.y *= r * (1.0f + wv.y);
    x.z *= r * (1.0f + wv.z);
    x.w *= r * (1.0f + wv.w);

    const int h0 = lane * 4;
    const int partner = (lane < 10) ? lane + 10 : ((lane < 20) ? lane - 10 : lane);
    float px = __shfl_sync(0xffffffffu, x.x, partner);
    float py = __shfl_sync(0xffffffffu, x.y, partner);
    float pz = __shfl_sync(0xffffffffu, x.z, partner);
    float pw = __shfl_sync(0xffffffffu, x.w, partner);

    if (h0 < 80) {
        const bool first = (h0 < 40);
        const float base_i = (float)(first ? h0 : h0 - 40);
        const float sgn = first ? -1.0f : 1.0f;
        float vals[4] = {x.x, x.y, x.z, x.w};
        float ps[4]   = {px, py, pz, pw};
        const float c2 = 0.49828921423310436f;    // log2(1e6)/40
#pragma unroll
        for (int j = 0; j < 4; j++) {
            float ts = exp2f((base_i + (float)j) * c2);
            float s, cc;
            sincosf(pos / ts, &s, &cc);
            vals[j] = vals[j] * cc + sgn * ps[j] * s;
        }
        x.x = vals[0]; x.y = vals[1]; x.z = vals[2]; x.w = vals[3];
    }
    return x;
}

__global__ void norm_rope_k_kernel(
    float* __restrict__ buf, const int* __restrict__ positions,
    const float* __restrict__ w)
{
    const int gw   = (blockIdx.x * blockDim.x + threadIdx.x) >> 5;
    const int lane = threadIdx.x & 31;
    const int kh = gw & 7;
    const int m  = gw >> 3;
    float* row = buf + (size_t)m * 1024 + kh * 128;
    float4 x = *reinterpret_cast<const float4*>(row + 4 * lane);
    x = norm_rope_row(x, w, lane, (float)positions[m]);
    *reinterpret_cast<float4*>(row + 4 * lane) = x;
}

__global__ void norm_rope_q_kernel(
    const float* __restrict__ q, const int* __restrict__ positions,
    const float* __restrict__ w, __half* __restrict__ qh)
{
    const int gw   = (blockIdx.x * blockDim.x + threadIdx.x) >> 5;
    const int lane = threadIdx.x & 31;
    const int n = gw & 31;
    const int m = gw >> 5;
    const float* row = q + (size_t)m * 4096 + n * 128;
    float4 x = *reinterpret_cast<const float4*>(row + 4 * lane);
    x = norm_rope_row(x, w, lane, (float)positions[m]);
    const float scale = 0.08838834764831845f * 1.4426950408889634f;
    const int b = m >> 10, t = m & 1023;
    __half2* o = reinterpret_cast<__half2*>(
        qh + ((size_t)((b * 32 + n) * 1024 + t)) * 128 + 4 * lane);
    o[0] = __floats2half2_rn(x.x * scale, x.y * scale);
    o[1] = __floats2half2_rn(x.z * scale, x.w * scale);
}

// ---------------------------------------------------------------------------
// K transpose -> half [h][s]
// ---------------------------------------------------------------------------
__global__ void transpose_k_half(const float* __restrict__ in,
                                 __half* __restrict__ out)
{
    __shared__ float tbuf[32][33];
    const int bk = blockIdx.y;
    const int b = bk >> 3, kh = bk & 7;
    const int th = (blockIdx.x & 3) * 32;
    const int ts = (blockIdx.x >> 2) * 32;
    const int x = threadIdx.x, y = threadIdx.y;
#pragma unroll
    for (int j = 0; j < 32; j += 8)
        tbuf[y + j][x] = in[(size_t)(b * 1024 + ts + y + j) * 1024 + kh * 128 + th + x];
    __syncthreads();
#pragma unroll
    for (int j = 0; j < 32; j += 8)
        out[(size_t)(bk * 128 + th + y + j) * 1024 + ts + x] =
            __float2half_rn(tbuf[x][y + j]);
}

// ---------------------------------------------------------------------------
// V reorder+convert -> half head-major
// ---------------------------------------------------------------------------
__global__ void v_reorder_half(const float* __restrict__ in,
                               __half* __restrict__ out)
{
    const int idx = (blockIdx.x * blockDim.x + threadIdx.x) * 4;
    const int h4 = idx & 1023;
    const int bs = idx >> 10;
    const int kh = h4 >> 7, h = h4 & 127;
    const int b = bs >> 10, s = bs & 1023;
    float4 v = *reinterpret_cast<const float4*>(in + idx);
    __half2* o = reinterpret_cast<__half2*>(
        out + ((size_t)((b * 8 + kh) * 1024 + s)) * 128 + h);
    o[0] = __floats2half2_rn(v.x, v.y);
    o[1] = __floats2half2_rn(v.z, v.w);
}

// ---------------------------------------------------------------------------
// Tensor-core flash attention (no gating). LPT order. Q staged through KV
// buffer 0 (fragments extracted in prologue) -> 64KB smem -> 3 CTAs/SM.
// ---------------------------------------------------------------------------
#define ATT_SMEM 65536
#define ONES_H2 0x3C003C00u

__global__ __launch_bounds__(128, 3) void attn_tc_kernel(
    const __half* __restrict__ qh, const __half* __restrict__ khT,
    const __half* __restrict__ vh, __half* __restrict__ outh)
{
    extern __shared__ char smem[];
    const uint32_t sbase = smem_u32(smem);
    const int tid  = threadIdx.x;
    const int wid  = tid >> 5;
    const int lane = tid & 31;
    const int g    = lane >> 2;
    const int c    = lane & 3;
    const int lrow = (lane & 7) + ((lane >> 3) & 1) * 8;
    const int lkc  = lane >> 4;

    const int qt = 15 - blockIdx.x;
    const int n  = blockIdx.y;
    const int b  = blockIdx.z;
    const int kh = n >> 2;
    const int bkh = b * 8 + kh;
    const int NT = qt + 1;

    auto load_kv = [&](int kt) {
        const uint32_t skb = sbase + (kt & 1) * 32768;
        const uint32_t svb = skb + 16384;
        const __half* kp = khT + ((size_t)bkh * 128) * 1024 + kt * 64;
#pragma unroll
        for (int j = 0; j < 8; j++) {
            int idx = tid + j * 128;
            int r = idx >> 3, ch = idx & 7;
            cp16(skb + r * 128 + ((ch ^ (r & 7)) * 16), kp + (size_t)r * 1024 + ch * 8);
        }
        const __half* vp = vh + ((size_t)(bkh * 1024 + kt * 64)) * 128;
#pragma unroll
        for (int j = 0; j < 8; j++) {
            int idx = tid + j * 128;
            int r = idx >> 4, ch = idx & 15;
            cp16(svb + r * 256 + ((ch ^ (r & 7)) * 16), vp + r * 128 + ch * 8);
        }
        asm volatile("cp.async.commit_group;" ::: "memory");
    };

    // ---- prologue: stage Q through buffer 0, extract fragments ----
    {
        const __half* qp = qh + ((size_t)((b * 32 + n) * 1024 + qt * 64)) * 128;
#pragma unroll
        for (int j = 0; j < 8; j++) {
            int idx = tid + j * 128;
            int r = idx >> 4, ch = idx & 15;
            cp16(sbase + r * 256 + ((ch ^ (r & 7)) * 16), qp + r * 128 + ch * 8);
        }
        asm volatile("cp.async.commit_group;" ::: "memory");
        asm volatile("cp.async.wait_group 0;" ::: "memory");
        __syncthreads();
    }
    uint32_t qa[8][4];
#pragma unroll
    for (int ks = 0; ks < 8; ks++) {
        int row = wid * 16 + lrow;
        ldsm4(qa[ks], sbase + row * 256 + (((ks * 2 + lkc) ^ (lrow & 7)) * 16));
    }
    __syncthreads();   // all warps done reading Q before buf0 is reused

    load_kv(0);
    if (NT > 1) load_kv(1);

    float o[16][4];
#pragma unroll
    for (int i = 0; i < 16; i++)
#pragma unroll
        for (int r = 0; r < 4; r++) o[i][r] = 0.0f;
    float ol[4] = {0.f, 0.f, 0.f, 0.f};
    float m0 = -3.4e38f, m1 = -3.4e38f;

    for (int kt = 0; kt < NT; kt++) {
        if (kt + 1 < NT) {
            asm volatile("cp.async.wait_group 1;" ::: "memory");
        } else {
            asm volatile("cp.async.wait_group 0;" ::: "memory");
        }
        __syncthreads();

        const uint32_t skb = sbase + (kt & 1) * 32768;
        const uint32_t svb = skb + 16384;

        float sc[8][4];
#pragma unroll
        for (int i = 0; i < 8; i++)
#pragma unroll
            for (int r = 0; r < 4; r++) sc[i][r] = 0.0f;

#pragma unroll
        for (int ks = 0; ks < 8; ks++) {
            uint32_t bk[4][4];
            int krow = ks * 16 + lrow;
#pragma unroll
            for (int p = 0; p < 4; p++) {
                int nc = p * 2 + lkc;
                ldsm4t(bk[p], skb + krow * 128 + ((nc ^ (krow & 7)) * 16));
            }
#pragma unroll
            for (int p = 0; p < 4; p++) {
                mma_f16(sc[2 * p],     qa[ks], bk[p][0], bk[p][1]);
                mma_f16(sc[2 * p + 1], qa[ks], bk[p][2], bk[p][3]);
            }
        }

        const int r0 = wid * 16 + g;
        if (kt == qt) {
#pragma unroll
            for (int j = 0; j < 8; j++) {
                int k0 = j * 8 + 2 * c;
                if (k0     > r0)     sc[j][0] = -1e30f;
                if (k0 + 1 > r0)     sc[j][1] = -1e30f;
                if (k0     > r0 + 8) sc[j][2] = -1e30f;
                if (k0 + 1 > r0 + 8) sc[j][3] = -1e30f;
            }
        }

        float mx0 = -3.4e38f, mx1 = -3.4e38f;
#pragma unroll
        for (int j = 0; j < 8; j++) {
            mx0 = fmaxf(mx0, fmaxf(sc[j][0], sc[j][1]));
            mx1 = fmaxf(mx1, fmaxf(sc[j][2], sc[j][3]));
        }
        mx0 = fmaxf(mx0, __shfl_xor_sync(0xffffffffu, mx0, 1));
        mx0 = fmaxf(mx0, __shfl_xor_sync(0xffffffffu, mx0, 2));
        mx1 = fmaxf(mx1, __shfl_xor_sync(0xffffffffu, mx1, 1));
        mx1 = fmaxf(mx1, __shfl_xor_sync(0xffffffffu, mx1, 2));

        float mn0 = fmaxf(m0, mx0), mn1 = fmaxf(m1, mx1);
        float a0 = ex2f(m0 - mn0), a1 = ex2f(m1 - mn1);
        m0 = mn0; m1 = mn1;

        uint32_t p_lo[8], p_hi[8];
#pragma unroll
        for (int j = 0; j < 8; j++) {
            p_lo[j] = ex2_h2(sc[j][1] - mn0, sc[j][0] - mn0);
            p_hi[j] = ex2_h2(sc[j][3] - mn1, sc[j][2] - mn1);
        }

        ol[0] *= a0; ol[1] *= a0; ol[2] *= a1; ol[3] *= a1;
#pragma unroll
        for (int i = 0; i < 16; i++) {
            o[i][0] *= a0; o[i][1] *= a0;
            o[i][2] *= a1; o[i][3] *= a1;
        }

#pragma unroll
        for (int j2 = 0; j2 < 4; j2++) {
            uint32_t pa[4] = { p_lo[2 * j2], p_hi[2 * j2],
                               p_lo[2 * j2 + 1], p_hi[2 * j2 + 1] };
            mma_f16(ol, pa, ONES_H2, ONES_H2);
            int krow = j2 * 16 + lrow;
#pragma unroll
            for (int p = 0; p < 8; p++) {
                uint32_t bv[4];
                int nc = p * 2 + lkc;
                ldsm4t(bv, svb + krow * 256 + ((nc ^ (krow & 7)) * 16));
                mma_f16(o[2 * p],     pa, bv[0], bv[1]);
                mma_f16(o[2 * p + 1], pa, bv[2], bv[3]);
            }
        }

        __syncthreads();
        if (kt + 2 < NT) load_kv(kt + 2);
    }

    const float inv0 = 1.0f / ol[0], inv1 = 1.0f / ol[2];
    const int tq0 = qt * 64 + wid * 16 + g;
    const int tq1 = tq0 + 8;
    __half* out0 = outh + (size_t)(b * 1024 + tq0) * 4096 + n * 128;
    __half* out1 = outh + (size_t)(b * 1024 + tq1) * 4096 + n * 128;
#pragma unroll
    for (int p = 0; p < 16; p++) {
        int col = p * 8 + 2 * c;
        *reinterpret_cast<__half2*>(out0 + col) =
            __floats2half2_rn(o[p][0] * inv0, o[p][1] * inv0);
        *reinterpret_cast<__half2*>(out1 + col) =
            __floats2half2_rn(o[p][2] * inv1, o[p][3] * inv1);
    }
}

// ---------------------------------------------------------------------------
// Launcher: R12 schedule (gate-GEMM released after wq conversion).
// ---------------------------------------------------------------------------
extern "C" void kernel_launch(void* const* d_in, const int* in_sizes, int n_in,
                              void* d_out, int out_size)
{
    const float* x   = (const float*)d_in[0];
    const int*   pos = (const int*)  d_in[1];
    const float* wq  = (const float*)d_in[2];
    const float* wk  = (const float*)d_in[3];
    const float* wv  = (const float*)d_in[4];
    const float* wo  = (const float*)d_in[5];
    const float* qw  = (const float*)d_in[6];
    const float* kw  = (const float*)d_in[7];
    float* out = (float*)d_out;

    float  *qb, *gateb, *kb, *vb;
    __half *xh, *wqh, *wkh, *wvh, *woh, *atth, *qh, *khT, *vh;
    cudaGetSymbolAddress((void**)&qb,    g_q);
    cudaGetSymbolAddress((void**)&gateb, g_gate);
    cudaGetSymbolAddress((void**)&kb,    g_k);
    cudaGetSymbolAddress((void**)&vb,    g_v);
    cudaGetSymbolAddress((void**)&xh,    g_xh);
    cudaGetSymbolAddress((void**)&wqh,   g_wqh);
    cudaGetSymbolAddress((void**)&wkh,   g_wkh);
    cudaGetSymbolAddress((void**)&wvh,   g_wvh);
    cudaGetSymbolAddress((void**)&woh,   g_woh);
    cudaGetSymbolAddress((void**)&atth,  g_atth);
    cudaGetSymbolAddress((void**)&qh,    g_qh);
    cudaGetSymbolAddress((void**)&khT,   g_khT);
    cudaGetSymbolAddress((void**)&vh,    g_vh);

    static bool attr_set = false;
    if (!attr_set) {
        cudaFuncSetAttribute(h16_gemm, cudaFuncAttributeMaxDynamicSharedMemorySize,
                             GEMM_SMEM);
        cudaFuncSetAttribute(attn_tc_kernel,
                             cudaFuncAttributeMaxDynamicSharedMemorySize, ATT_SMEM);
        attr_set = true;
    }

    cudaStream_t s0 = 0;

    cudaEventRecord(hxs.e_root, s0);
    cudaStreamWaitEvent(hxs.s1, hxs.e_root, 0);
    cudaStreamWaitEvent(hxs.s2, hxs.e_root, 0);
    cudaStreamWaitEvent(hxs.s3, hxs.e_root, 0);

    // s3: wo conversion first (needed only at the very end)
    f2h_kernel<<<(4096UL * 4096) / 4096, 256, 0, hxs.s3>>>(wo, woh);

    // main: x conversion -> fork
    f2h_kernel<<<(4096UL * 4096) / 4096, 256, 0, s0>>>(x, xh);
    cudaEventRecord(hxs.e_x, s0);
    cudaStreamWaitEvent(hxs.s1, hxs.e_x, 0);
    cudaStreamWaitEvent(hxs.s2, hxs.e_x, 0);

    // s1: K chain
    f2h_kernel<<<(4096UL * 1024) / 4096, 256, 0, hxs.s1>>>(wk, wkh);
    h16_gemm<<<dim3(8, 32), 256, GEMM_SMEM, hxs.s1>>>(
        xh, wkh, kb, 4096, 1024, 4096, 1024, 1);
    norm_rope_k_kernel<<<(4096 * 8) / 8, 256, 0, hxs.s1>>>(kb, pos, kw);
    transpose_k_half<<<dim3(128, 32), dim3(32, 8), 0, hxs.s1>>>(kb, khT);
    cudaEventRecord(hxs.e_k, hxs.s1);

    // s2: V chain
    f2h_kernel<<<(4096UL * 1024) / 4096, 256, 0, hxs.s2>>>(wv, wvh);
    h16_gemm<<<dim3(8, 32), 256, GEMM_SMEM, hxs.s2>>>(
        xh, wvh, vb, 4096, 1024, 4096, 1024, 1);
    v_reorder_half<<<(4096UL * 1024) / 1024, 256, 0, hxs.s2>>>(vb, vh);
    cudaEventRecord(hxs.e_v, hxs.s2);

    // main: wq conversion, q-GEMM (strided: head n -> wq cols n*256..+127)
    f2h_kernel<<<(4096UL * 8192) / 4096, 256, 0, s0>>>(wq, wqh);
    cudaEventRecord(hxs.e_wq, s0);
    h16_gemm<<<dim3(32, 32), 256, GEMM_SMEM, s0>>>(
        xh, wqh, qb, 4096, 4096, 4096, 8192, 2);
    norm_rope_q_kernel<<<(4096 * 32) / 8, 256, 0, s0>>>(qb, pos, qw, qh);

    // s3: gate-GEMM (wq cols n*256+128..+255)
    cudaStreamWaitEvent(hxs.s3, hxs.e_wq, 0);
    h16_gemm<<<dim3(32, 32), 256, GEMM_SMEM, hxs.s3>>>(
        xh, wqh + 128, gateb, 4096, 4096, 4096, 8192, 2);
    cudaEventRecord(hxs.e_gate, hxs.s3);

    // main: join K/V, attention (ungated output)
    cudaStreamWaitEvent(s0, hxs.e_k, 0);
    cudaStreamWaitEvent(s0, hxs.e_v, 0);
    attn_tc_kernel<<<dim3(16, 32, 4), 128, ATT_SMEM, s0>>>(qh, khT, vh, atth);

    // join gate-GEMM (also orders woh), apply gate, out-projection
    cudaStreamWaitEvent(s0, hxs.e_gate, 0);
    gate_apply_kernel<<<(4096UL * 4096) / 2048, 256, 0, s0>>>(atth, gateb);
    h16_gemm<<<dim3(32, 32), 256, GEMM_SMEM, s0>>>(
        atth, woh, out, 4096, 4096, 4096, 4096, 1);
}

// round 15
// speedup vs baseline: 1.0610x; 1.0214x over previous
#include <cuda_runtime.h>
#include <cuda_fp16.h>
#include <cstdint>
#include <math.h>

// ============================================================================
// Shapes: B=4, T=1024, D=4096, N=32 heads, KH=8 kv heads, H=128, G=4
// ============================================================================

__device__ float  g_q   [4096UL * 4096];  // [t][n*128] q fp32 (dense)
__device__ float  g_gate[4096UL * 4096];  // [t][n*128] sigmoid(gate) fp32
__device__ float  g_k  [4096UL * 1024];
__device__ float  g_v  [4096UL * 1024];
__device__ __half g_xh  [4096UL * 4096];
__device__ __half g_wqh [4096UL * 8192];
__device__ __half g_wkh [4096UL * 1024];
__device__ __half g_wvh [4096UL * 1024];
__device__ __half g_woh [4096UL * 4096];
__device__ __half g_atth[4096UL * 4096];
__device__ __half g_qh  [131072UL * 128];
__device__ __half g_khT [32UL * 128 * 1024];
__device__ __half g_vh  [32UL * 1024 * 128];

struct HxStreams {
    cudaStream_t s1, s2, s3;
    cudaEvent_t e_root, e_x, e_wq, e_k, e_v, e_gate;
    HxStreams() {
        cudaStreamCreateWithFlags(&s1, cudaStreamNonBlocking);
        cudaStreamCreateWithFlags(&s2, cudaStreamNonBlocking);
        cudaStreamCreateWithFlags(&s3, cudaStreamNonBlocking);
        cudaEventCreateWithFlags(&e_root, cudaEventDisableTiming);
        cudaEventCreateWithFlags(&e_x,    cudaEventDisableTiming);
        cudaEventCreateWithFlags(&e_wq,   cudaEventDisableTiming);
        cudaEventCreateWithFlags(&e_k,    cudaEventDisableTiming);
        cudaEventCreateWithFlags(&e_v,    cudaEventDisableTiming);
        cudaEventCreateWithFlags(&e_gate, cudaEventDisableTiming);
    }
};
static HxStreams hxs;

__device__ __forceinline__ uint32_t smem_u32(const void* p) {
    uint32_t a;
    asm("{ .reg .u64 t; cvta.to.shared.u64 t, %1; cvt.u32.u64 %0, t; }"
        : "=r"(a) : "l"(p));
    return a;
}
__device__ __forceinline__ void cp16(uint32_t dst_smem, const void* src) {
    asm volatile("cp.async.cg.shared.global [%0], [%1], 16;"
                 :: "r"(dst_smem), "l"(src));
}
__device__ __forceinline__ void ldsm4(uint32_t* r, uint32_t addr) {
    asm volatile("ldmatrix.sync.aligned.m8n8.x4.shared.b16 {%0,%1,%2,%3}, [%4];"
                 : "=r"(r[0]), "=r"(r[1]), "=r"(r[2]), "=r"(r[3]) : "r"(addr));
}
__device__ __forceinline__ void ldsm4t(uint32_t* r, uint32_t addr) {
    asm volatile("ldmatrix.sync.aligned.m8n8.x4.trans.shared.b16 {%0,%1,%2,%3}, [%4];"
                 : "=r"(r[0]), "=r"(r[1]), "=r"(r[2]), "=r"(r[3]) : "r"(addr));
}
__device__ __forceinline__ void mma_f16(float* d, const uint32_t* a,
                                        uint32_t b0, uint32_t b1) {
    asm volatile(
        "mma.sync.aligned.m16n8k16.row.col.f32.f16.f16.f32 "
        "{%0,%1,%2,%3}, {%4,%5,%6,%7}, {%8,%9}, {%0,%1,%2,%3};"
        : "+f"(d[0]), "+f"(d[1]), "+f"(d[2]), "+f"(d[3])
        : "r"(a[0]), "r"(a[1]), "r"(a[2]), "r"(a[3]), "r"(b0), "r"(b1));
}
__device__ __forceinline__ uint32_t ex2_h2(float hi, float lo) {
    uint32_t h, d;
    asm("cvt.rn.f16x2.f32 %0, %1, %2;" : "=r"(h) : "f"(hi), "f"(lo));
    asm("ex2.approx.f16x2 %0, %1;" : "=r"(d) : "r"(h));
    return d;
}
__device__ __forceinline__ float ex2f(float x) {
    float r;
    asm("ex2.approx.f32 %0, %1;" : "=f"(r) : "f"(x));
    return r;
}

// ---------------------------------------------------------------------------
// fp16 mma.sync GEMM with strided-B (colmul), dense C. do_sigmoid=1 applies
// sigmoid in the epilogue (hides MUFU in a tensor-bound kernel).
// CTA 128x128, BK=64, 2 CTAs/SM, 3-stage cp.async, single sync/iter.
// ---------------------------------------------------------------------------
#define BM 128
#define BN 128
#define BK 64
#define STAGES 3
#define A_BYTES (128 * 128)
#define B_BYTES (64 * 256)
#define STAGE_BYTES (A_BYTES + B_BYTES)
#define GEMM_SMEM (STAGES * STAGE_BYTES)

__global__ __launch_bounds__(256, 2) void h16_gemm(
    const __half* __restrict__ A, const __half* __restrict__ B,
    float* __restrict__ C, int M, int N, int K, int ldb, int colmul,
    int do_sigmoid)
{
    extern __shared__ char smem[];
    const uint32_t sbase = smem_u32(smem);
    const int tid  = threadIdx.x;
    const int wid  = tid >> 5;
    const int lane = tid & 31;
    const int g    = lane >> 2;
    const int c    = lane & 3;

    const int m0 = blockIdx.y * BM;
    const int n0 = blockIdx.x * BN;
    const int m_warp = (wid & 1) * 64;
    const int n_warp = (wid >> 1) * 32;
    const int NKT = K / BK;

    float acc[4][4][4];
#pragma unroll
    for (int i = 0; i < 4; i++)
#pragma unroll
        for (int j = 0; j < 4; j++)
#pragma unroll
            for (int r = 0; r < 4; r++) acc[i][j][r] = 0.0f;

    const int ar  = tid >> 1;
    const int ac  = tid & 1;
    const int brr = tid >> 2;
    const int bcg = tid & 3;

    const int lrow = (lane & 7) + ((lane >> 3) & 1) * 8;
    const int lkc  = lane >> 4;
    const int lxor = lane & 7;

    auto load_tile = [&](int kt) {
        const uint32_t sa = sbase + (kt % STAGES) * STAGE_BYTES;
        const uint32_t sb = sa + A_BYTES;
        const int k0 = kt * BK;
        const __half* ap = A + (size_t)(m0 + ar) * K + k0 + ac * 32;
#pragma unroll
        for (int j = 0; j < 4; j++) {
            int ch = ac * 4 + j;
            cp16(sa + ar * 128 + ((ch ^ (ar & 7)) * 16), ap + j * 8);
        }
        const __half* bp = B + (size_t)(k0 + brr) * ldb + n0 * colmul + bcg * 32;
#pragma unroll
        for (int j = 0; j < 4; j++) {
            int ch = bcg * 4 + j;
            cp16(sb + brr * 256 + ((ch ^ (brr & 7)) * 16), bp + j * 8);
        }
        asm volatile("cp.async.commit_group;" ::: "memory");
    };

#pragma unroll
    for (int s = 0; s < STAGES - 1; s++) load_tile(s);

    for (int kt = 0; kt < NKT; kt++) {
        if (kt + STAGES - 1 < NKT) {
            asm volatile("cp.async.wait_group %0;" :: "n"(STAGES - 2) : "memory");
        } else {
            asm volatile("cp.async.wait_group 0;" ::: "memory");
        }
        __syncthreads();
        if (kt + STAGES - 1 < NKT) load_tile(kt + STAGES - 1);

        const uint32_t sa = sbase + (kt % STAGES) * STAGE_BYTES;
        const uint32_t sb = sa + A_BYTES;

#pragma unroll
        for (int ks = 0; ks < BK / 16; ks++) {
            uint32_t a[4][4], b[2][4];
#pragma unroll
            for (int mt = 0; mt < 4; mt++) {
                int row = m_warp + mt * 16 + lrow;
                ldsm4(a[mt], sa + row * 128 + (((ks * 2 + lkc) ^ lxor) * 16));
            }
#pragma unroll
            for (int p = 0; p < 2; p++) {
                int krow = ks * 16 + lrow;
                int nc = (n_warp >> 3) + p * 2 + lkc;
                ldsm4t(b[p], sb + krow * 256 + ((nc ^ (krow & 7)) * 16));
            }
#pragma unroll
            for (int mt = 0; mt < 4; mt++)
#pragma unroll
                for (int p = 0; p < 2; p++) {
                    mma_f16(acc[mt][2 * p],     a[mt], b[p][0], b[p][1]);
                    mma_f16(acc[mt][2 * p + 1], a[mt], b[p][2], b[p][3]);
                }
        }
    }

    if (do_sigmoid) {
#pragma unroll
        for (int mt = 0; mt < 4; mt++)
#pragma unroll
            for (int nt = 0; nt < 4; nt++)
#pragma unroll
                for (int r = 0; r < 4; r++)
                    acc[mt][nt][r] = 1.0f / (1.0f + __expf(-acc[mt][nt][r]));
    }

#pragma unroll
    for (int mt = 0; mt < 4; mt++) {
        const int row = m0 + m_warp + mt * 16 + g;
#pragma unroll
        for (int nt = 0; nt < 4; nt++) {
            const int col = n0 + n_warp + nt * 8 + c * 2;
            *reinterpret_cast<float2*>(&C[(size_t)row * N + col]) =
                make_float2(acc[mt][nt][0], acc[mt][nt][1]);
            *reinterpret_cast<float2*>(&C[(size_t)(row + 8) * N + col]) =
                make_float2(acc[mt][nt][2], acc[mt][nt][3]);
        }
    }
}

// ---------------------------------------------------------------------------
// float -> half conversion, 64B per thread
// ---------------------------------------------------------------------------
__global__ void f2h_kernel(const float* __restrict__ in, __half* __restrict__ out)
{
    const int i = (blockIdx.x * blockDim.x + threadIdx.x) * 16;
#pragma unroll
    for (int j = 0; j < 4; j++) {
        float4 v = *reinterpret_cast<const float4*>(in + i + j * 4);
        *reinterpret_cast<__half2*>(out + i + j * 4)     = __floats2half2_rn(v.x, v.y);
        *reinterpret_cast<__half2*>(out + i + j * 4 + 2) = __floats2half2_rn(v.z, v.w);
    }
}

// ---------------------------------------------------------------------------
// Gate multiply: atth *= gates (sigmoid precomputed in gate-GEMM epilogue)
// ---------------------------------------------------------------------------
__global__ void gate_apply_kernel(__half* __restrict__ o,
                                  const float* __restrict__ gates)
{
    const int i = (blockIdx.x * blockDim.x + threadIdx.x) * 8;
#pragma unroll
    for (int j = 0; j < 2; j++) {
        float4 gv = *reinterpret_cast<const float4*>(gates + i + j * 4);
        __half2 h0 = *reinterpret_cast<__half2*>(o + i + j * 4);
        __half2 h1 = *reinterpret_cast<__half2*>(o + i + j * 4 + 2);
        float2 f0 = __half22float2(h0);
        float2 f1 = __half22float2(h1);
        f0.x *= gv.x; f0.y *= gv.y;
        f1.x *= gv.z; f1.y *= gv.w;
        *reinterpret_cast<__half2*>(o + i + j * 4)     = __floats2half2_rn(f0.x, f0.y);
        *reinterpret_cast<__half2*>(o + i + j * 4 + 2) = __floats2half2_rn(f1.x, f1.y);
    }
}

// ---------------------------------------------------------------------------
// RMSNorm + RoPE core
// ---------------------------------------------------------------------------
__device__ __forceinline__ float4 norm_rope_row(
    float4 x, const float* __restrict__ w, int lane, float pos)
{
    float ss = x.x*x.x + x.y*x.y + x.z*x.z + x.w*x.w;
#pragma unroll
    for (int o = 16; o; o >>= 1) ss += __shfl_xor_sync(0xffffffffu, ss, o);
    float r = rsqrtf(ss * (1.0f / 128.0f) + 1e-6f);
    float4 wv = *reinterpret_cast<const float4*>(w + 4 * lane);
    x.x *= r * (1.0f + wv.x);
    x.y *= r * (1.0f + wv.y);
    x.z *= r * (1.0f + wv.z);
    x.w *= r * (1.0f + wv.w);

    const int h0 = lane * 4;
    const int partner = (lane < 10) ? lane + 10 : ((lane < 20) ? lane - 10 : lane);
    float px = __shfl_sync(0xffffffffu, x.x, partner);
    float py = __shfl_sync(0xffffffffu, x.y, partner);
    float pz = __shfl_sync(0xffffffffu, x.z, partner);
    float pw = __shfl_sync(0xffffffffu, x.w, partner);

    if (h0 < 80) {
        const bool first = (h0 < 40);
        const float base_i = (float)(first ? h0 : h0 - 40);
        const float sgn = first ? -1.0f : 1.0f;
        float vals[4] = {x.x, x.y, x.z, x.w};
        float ps[4]   = {px, py, pz, pw};
        const float c2 = 0.49828921423310436f;    // log2(1e6)/40
#pragma unroll
        for (int j = 0; j < 4; j++) {
            float ts = exp2f((base_i + (float)j) * c2);
            float s, cc;
            sincosf(pos / ts, &s, &cc);
            vals[j] = vals[j] * cc + sgn * ps[j] * s;
        }
        x.x = vals[0]; x.y = vals[1]; x.z = vals[2]; x.w = vals[3];
    }
    return x;
}

__global__ void norm_rope_k_kernel(
    float* __restrict__ buf, const int* __restrict__ positions,
    const float* __restrict__ w)
{
    const int gw   = (blockIdx.x * blockDim.x + threadIdx.x) >> 5;
    const int lane = threadIdx.x & 31;
    const int kh = gw & 7;
    const int m  = gw >> 3;
    float* row = buf + (size_t)m * 1024 + kh * 128;
    float4 x = *reinterpret_cast<const float4*>(row + 4 * lane);
    x = norm_rope_row(x, w, lane, (float)positions[m]);
    *reinterpret_cast<float4*>(row + 4 * lane) = x;
}

__global__ void norm_rope_q_kernel(
    const float* __restrict__ q, const int* __restrict__ positions,
    const float* __restrict__ w, __half* __restrict__ qh)
{
    const int gw   = (blockIdx.x * blockDim.x + threadIdx.x) >> 5;
    const int lane = threadIdx.x & 31;
    const int n = gw & 31;
    const int m = gw >> 5;
    const float* row = q + (size_t)m * 4096 + n * 128;
    float4 x = *reinterpret_cast<const float4*>(row + 4 * lane);
    x = norm_rope_row(x, w, lane, (float)positions[m]);
    const float scale = 0.08838834764831845f * 1.4426950408889634f;
    const int b = m >> 10, t = m & 1023;
    __half2* o = reinterpret_cast<__half2*>(
        qh + ((size_t)((b * 32 + n) * 1024 + t)) * 128 + 4 * lane);
    o[0] = __floats2half2_rn(x.x * scale, x.y * scale);
    o[1] = __floats2half2_rn(x.z * scale, x.w * scale);
}

// ---------------------------------------------------------------------------
// K transpose -> half [h][s]
// ---------------------------------------------------------------------------
__global__ void transpose_k_half(const float* __restrict__ in,
                                 __half* __restrict__ out)
{
    __shared__ float tbuf[32][33];
    const int bk = blockIdx.y;
    const int b = bk >> 3, kh = bk & 7;
    const int th = (blockIdx.x & 3) * 32;
    const int ts = (blockIdx.x >> 2) * 32;
    const int x = threadIdx.x, y = threadIdx.y;
#pragma unroll
    for (int j = 0; j < 32; j += 8)
        tbuf[y + j][x] = in[(size_t)(b * 1024 + ts + y + j) * 1024 + kh * 128 + th + x];
    __syncthreads();
#pragma unroll
    for (int j = 0; j < 32; j += 8)
        out[(size_t)(bk * 128 + th + y + j) * 1024 + ts + x] =
            __float2half_rn(tbuf[x][y + j]);
}

// ---------------------------------------------------------------------------
// V reorder+convert -> half head-major
// ---------------------------------------------------------------------------
__global__ void v_reorder_half(const float* __restrict__ in,
                               __half* __restrict__ out)
{
    const int idx = (blockIdx.x * blockDim.x + threadIdx.x) * 4;
    const int h4 = idx & 1023;
    const int bs = idx >> 10;
    const int kh = h4 >> 7, h = h4 & 127;
    const int b = bs >> 10, s = bs & 1023;
    float4 v = *reinterpret_cast<const float4*>(in + idx);
    __half2* o = reinterpret_cast<__half2*>(
        out + ((size_t)((b * 8 + kh) * 1024 + s)) * 128 + h);
    o[0] = __floats2half2_rn(v.x, v.y);
    o[1] = __floats2half2_rn(v.z, v.w);
}

// ---------------------------------------------------------------------------
// Tensor-core flash attention (no gating). LPT order. Q staged through KV
// buffer 0 -> 64KB smem -> 3 CTAs/SM.
// ---------------------------------------------------------------------------
#define ATT_SMEM 65536
#define ONES_H2 0x3C003C00u

__global__ __launch_bounds__(128, 3) void attn_tc_kernel(
    const __half* __restrict__ qh, const __half* __restrict__ khT,
    const __half* __restrict__ vh, __half* __restrict__ outh)
{
    extern __shared__ char smem[];
    const uint32_t sbase = smem_u32(smem);
    const int tid  = threadIdx.x;
    const int wid  = tid >> 5;
    const int lane = tid & 31;
    const int g    = lane >> 2;
    const int c    = lane & 3;
    const int lrow = (lane & 7) + ((lane >> 3) & 1) * 8;
    const int lkc  = lane >> 4;

    const int qt = 15 - blockIdx.x;
    const int n  = blockIdx.y;
    const int b  = blockIdx.z;
    const int kh = n >> 2;
    const int bkh = b * 8 + kh;
    const int NT = qt + 1;

    auto load_kv = [&](int kt) {
        const uint32_t skb = sbase + (kt & 1) * 32768;
        const uint32_t svb = skb + 16384;
        const __half* kp = khT + ((size_t)bkh * 128) * 1024 + kt * 64;
#pragma unroll
        for (int j = 0; j < 8; j++) {
            int idx = tid + j * 128;
            int r = idx >> 3, ch = idx & 7;
            cp16(skb + r * 128 + ((ch ^ (r & 7)) * 16), kp + (size_t)r * 1024 + ch * 8);
        }
        const __half* vp = vh + ((size_t)(bkh * 1024 + kt * 64)) * 128;
#pragma unroll
        for (int j = 0; j < 8; j++) {
            int idx = tid + j * 128;
            int r = idx >> 4, ch = idx & 15;
            cp16(svb + r * 256 + ((ch ^ (r & 7)) * 16), vp + r * 128 + ch * 8);
        }
        asm volatile("cp.async.commit_group;" ::: "memory");
    };

    // prologue: stage Q through buffer 0, extract fragments
    {
        const __half* qp = qh + ((size_t)((b * 32 + n) * 1024 + qt * 64)) * 128;
#pragma unroll
        for (int j = 0; j < 8; j++) {
            int idx = tid + j * 128;
            int r = idx >> 4, ch = idx & 15;
            cp16(sbase + r * 256 + ((ch ^ (r & 7)) * 16), qp + r * 128 + ch * 8);
        }
        asm volatile("cp.async.commit_group;" ::: "memory");
        asm volatile("cp.async.wait_group 0;" ::: "memory");
        __syncthreads();
    }
    uint32_t qa[8][4];
#pragma unroll
    for (int ks = 0; ks < 8; ks++) {
        int row = wid * 16 + lrow;
        ldsm4(qa[ks], sbase + row * 256 + (((ks * 2 + lkc) ^ (lrow & 7)) * 16));
    }
    __syncthreads();

    load_kv(0);
    if (NT > 1) load_kv(1);

    float o[16][4];
#pragma unroll
    for (int i = 0; i < 16; i++)
#pragma unroll
        for (int r = 0; r < 4; r++) o[i][r] = 0.0f;
    float ol[4] = {0.f, 0.f, 0.f, 0.f};
    float m0 = -3.4e38f, m1 = -3.4e38f;

    for (int kt = 0; kt < NT; kt++) {
        if (kt + 1 < NT) {
            asm volatile("cp.async.wait_group 1;" ::: "memory");
        } else {
            asm volatile("cp.async.wait_group 0;" ::: "memory");
        }
        __syncthreads();

        const uint32_t skb = sbase + (kt & 1) * 32768;
        const uint32_t svb = skb + 16384;

        float sc[8][4];
#pragma unroll
        for (int i = 0; i < 8; i++)
#pragma unroll
            for (int r = 0; r < 4; r++) sc[i][r] = 0.0f;

#pragma unroll
        for (int ks = 0; ks < 8; ks++) {
            uint32_t bk[4][4];
            int krow = ks * 16 + lrow;
#pragma unroll
            for (int p = 0; p < 4; p++) {
                int nc = p * 2 + lkc;
                ldsm4t(bk[p], skb + krow * 128 + ((nc ^ (krow & 7)) * 16));
            }
#pragma unroll
            for (int p = 0; p < 4; p++) {
                mma_f16(sc[2 * p],     qa[ks], bk[p][0], bk[p][1]);
                mma_f16(sc[2 * p + 1], qa[ks], bk[p][2], bk[p][3]);
            }
        }

        const int r0 = wid * 16 + g;
        if (kt == qt) {
#pragma unroll
            for (int j = 0; j < 8; j++) {
                int k0 = j * 8 + 2 * c;
                if (k0     > r0)     sc[j][0] = -1e30f;
                if (k0 + 1 > r0)     sc[j][1] = -1e30f;
                if (k0     > r0 + 8) sc[j][2] = -1e30f;
                if (k0 + 1 > r0 + 8) sc[j][3] = -1e30f;
            }
        }

        float mx0 = -3.4e38f, mx1 = -3.4e38f;
#pragma unroll
        for (int j = 0; j < 8; j++) {
            mx0 = fmaxf(mx0, fmaxf(sc[j][0], sc[j][1]));
            mx1 = fmaxf(mx1, fmaxf(sc[j][2], sc[j][3]));
        }
        mx0 = fmaxf(mx0, __shfl_xor_sync(0xffffffffu, mx0, 1));
        mx0 = fmaxf(mx0, __shfl_xor_sync(0xffffffffu, mx0, 2));
        mx1 = fmaxf(mx1, __shfl_xor_sync(0xffffffffu, mx1, 1));
        mx1 = fmaxf(mx1, __shfl_xor_sync(0xffffffffu, mx1, 2));

        float mn0 = fmaxf(m0, mx0), mn1 = fmaxf(m1, mx1);
        float a0 = ex2f(m0 - mn0), a1 = ex2f(m1 - mn1);
        m0 = mn0; m1 = mn1;

        uint32_t p_lo[8], p_hi[8];
#pragma unroll
        for (int j = 0; j < 8; j++) {
            p_lo[j] = ex2_h2(sc[j][1] - mn0, sc[j][0] - mn0);
            p_hi[j] = ex2_h2(sc[j][3] - mn1, sc[j][2] - mn1);
        }

        ol[0] *= a0; ol[1] *= a0; ol[2] *= a1; ol[3] *= a1;
#pragma unroll
        for (int i = 0; i < 16; i++) {
            o[i][0] *= a0; o[i][1] *= a0;
            o[i][2] *= a1; o[i][3] *= a1;
        }

#pragma unroll
        for (int j2 = 0; j2 < 4; j2++) {
            uint32_t pa[4] = { p_lo[2 * j2], p_hi[2 * j2],
                               p_lo[2 * j2 + 1], p_hi[2 * j2 + 1] };
            mma_f16(ol, pa, ONES_H2, ONES_H2);
            int krow = j2 * 16 + lrow;
#pragma unroll
            for (int p = 0; p < 8; p++) {
                uint32_t bv[4];
                int nc = p * 2 + lkc;
                ldsm4t(bv, svb + krow * 256 + ((nc ^ (krow & 7)) * 16));
                mma_f16(o[2 * p],     pa, bv[0], bv[1]);
                mma_f16(o[2 * p + 1], pa, bv[2], bv[3]);
            }
        }

        __syncthreads();
        if (kt + 2 < NT) load_kv(kt + 2);
    }

    const float inv0 = 1.0f / ol[0], inv1 = 1.0f / ol[2];
    const int tq0 = qt * 64 + wid * 16 + g;
    const int tq1 = tq0 + 8;
    __half* out0 = outh + (size_t)(b * 1024 + tq0) * 4096 + n * 128;
    __half* out1 = outh + (size_t)(b * 1024 + tq1) * 4096 + n * 128;
#pragma unroll
    for (int p = 0; p < 16; p++) {
        int col = p * 8 + 2 * c;
        *reinterpret_cast<__half2*>(out0 + col) =
            __floats2half2_rn(o[p][0] * inv0, o[p][1] * inv0);
        *reinterpret_cast<__half2*>(out1 + col) =
            __floats2half2_rn(o[p][2] * inv1, o[p][3] * inv1);
    }
}

// ---------------------------------------------------------------------------
// Launcher: weight conversions start at root (parallel with x conversion);
// sigmoid folded into gate-GEMM epilogue; gate_apply is a pure multiply.
// ---------------------------------------------------------------------------
extern "C" void kernel_launch(void* const* d_in, const int* in_sizes, int n_in,
                              void* d_out, int out_size)
{
    const float* x   = (const float*)d_in[0];
    const int*   pos = (const int*)  d_in[1];
    const float* wq  = (const float*)d_in[2];
    const float* wk  = (const float*)d_in[3];
    const float* wv  = (const float*)d_in[4];
    const float* wo  = (const float*)d_in[5];
    const float* qw  = (const float*)d_in[6];
    const float* kw  = (const float*)d_in[7];
    float* out = (float*)d_out;

    float  *qb, *gateb, *kb, *vb;
    __half *xh, *wqh, *wkh, *wvh, *woh, *atth, *qh, *khT, *vh;
    cudaGetSymbolAddress((void**)&qb,    g_q);
    cudaGetSymbolAddress((void**)&gateb, g_gate);
    cudaGetSymbolAddress((void**)&kb,    g_k);
    cudaGetSymbolAddress((void**)&vb,    g_v);
    cudaGetSymbolAddress((void**)&xh,    g_xh);
    cudaGetSymbolAddress((void**)&wqh,   g_wqh);
    cudaGetSymbolAddress((void**)&wkh,   g_wkh);
    cudaGetSymbolAddress((void**)&wvh,   g_wvh);
    cudaGetSymbolAddress((void**)&woh,   g_woh);
    cudaGetSymbolAddress((void**)&atth,  g_atth);
    cudaGetSymbolAddress((void**)&qh,    g_qh);
    cudaGetSymbolAddress((void**)&khT,   g_khT);
    cudaGetSymbolAddress((void**)&vh,    g_vh);

    static bool attr_set = false;
    if (!attr_set) {
        cudaFuncSetAttribute(h16_gemm, cudaFuncAttributeMaxDynamicSharedMemorySize,
                             GEMM_SMEM);
        cudaFuncSetAttribute(attn_tc_kernel,
                             cudaFuncAttributeMaxDynamicSharedMemorySize, ATT_SMEM);
        attr_set = true;
    }

    cudaStream_t s0 = 0;

    cudaEventRecord(hxs.e_root, s0);
    cudaStreamWaitEvent(hxs.s1, hxs.e_root, 0);
    cudaStreamWaitEvent(hxs.s2, hxs.e_root, 0);
    cudaStreamWaitEvent(hxs.s3, hxs.e_root, 0);

    // main: x conversion
    f2h_kernel<<<(4096UL * 4096) / 4096, 256, 0, s0>>>(x, xh);
    cudaEventRecord(hxs.e_x, s0);

    // s3: wq conversion at root (parallel with x), then wo conversion
    f2h_kernel<<<(4096UL * 8192) / 4096, 256, 0, hxs.s3>>>(wq, wqh);
    cudaEventRecord(hxs.e_wq, hxs.s3);
    f2h_kernel<<<(4096UL * 4096) / 4096, 256, 0, hxs.s3>>>(wo, woh);

    // s1: K chain (wk conversion at root; GEMM waits for x)
    f2h_kernel<<<(4096UL * 1024) / 4096, 256, 0, hxs.s1>>>(wk, wkh);
    cudaStreamWaitEvent(hxs.s1, hxs.e_x, 0);
    h16_gemm<<<dim3(8, 32), 256, GEMM_SMEM, hxs.s1>>>(
        xh, wkh, kb, 4096, 1024, 4096, 1024, 1, 0);
    norm_rope_k_kernel<<<(4096 * 8) / 8, 256, 0, hxs.s1>>>(kb, pos, kw);
    transpose_k_half<<<dim3(128, 32), dim3(32, 8), 0, hxs.s1>>>(kb, khT);
    cudaEventRecord(hxs.e_k, hxs.s1);

    // s2: V chain
    f2h_kernel<<<(4096UL * 1024) / 4096, 256, 0, hxs.s2>>>(wv, wvh);
    cudaStreamWaitEvent(hxs.s2, hxs.e_x, 0);
    h16_gemm<<<dim3(8, 32), 256, GEMM_SMEM, hxs.s2>>>(
        xh, wvh, vb, 4096, 1024, 4096, 1024, 1, 0);
    v_reorder_half<<<(4096UL * 1024) / 1024, 256, 0, hxs.s2>>>(vb, vh);
    cudaEventRecord(hxs.e_v, hxs.s2);

    // main: q-GEMM (waits wq conversion), norm
    cudaStreamWaitEvent(s0, hxs.e_wq, 0);
    h16_gemm<<<dim3(32, 32), 256, GEMM_SMEM, s0>>>(
        xh, wqh, qb, 4096, 4096, 4096, 8192, 2, 0);
    norm_rope_q_kernel<<<(4096 * 32) / 8, 256, 0, s0>>>(qb, pos, qw, qh);

    // s3: gate-GEMM with fused sigmoid (waits x; wqh ordered on s3)
    cudaStreamWaitEvent(hxs.s3, hxs.e_x, 0);
    h16_gemm<<<dim3(32, 32), 256, GEMM_SMEM, hxs.s3>>>(
        xh, wqh + 128, gateb, 4096, 4096, 4096, 8192, 2, 1);
    cudaEventRecord(hxs.e_gate, hxs.s3);

    // main: join K/V, attention (ungated output)
    cudaStreamWaitEvent(s0, hxs.e_k, 0);
    cudaStreamWaitEvent(s0, hxs.e_v, 0);
    attn_tc_kernel<<<dim3(16, 32, 4), 128, ATT_SMEM, s0>>>(qh, khT, vh, atth);

    // join gate-GEMM (also orders woh), apply gate multiply, out-projection
    cudaStreamWaitEvent(s0, hxs.e_gate, 0);
    gate_apply_kernel<<<(4096UL * 4096) / 2048, 256, 0, s0>>>(atth, gateb);
    h16_gemm<<<dim3(32, 32), 256, GEMM_SMEM, s0>>>(
        atth, woh, out, 4096, 4096, 4096, 4096, 1, 0);
}

// round 16
// speedup vs baseline: 1.0657x; 1.0045x over previous
#include <cuda_runtime.h>
#include <cuda_fp16.h>
#include <cstdint>
#include <math.h>

// ============================================================================
// Shapes: B=4, T=1024, D=4096, N=32 heads, KH=8 kv heads, H=128, G=4
// ============================================================================

__device__ float  g_q   [4096UL * 4096];  // [t][n*128] q fp32 (dense)
__device__ float  g_gate[4096UL * 4096];  // [t][n*128] sigmoid(gate) fp32
__device__ float  g_k  [4096UL * 1024];
__device__ float  g_v  [4096UL * 1024];
__device__ __half g_xh  [4096UL * 4096];
__device__ __half g_wqh [4096UL * 8192];
__device__ __half g_wkh [4096UL * 1024];
__device__ __half g_wvh [4096UL * 1024];
__device__ __half g_woh [4096UL * 4096];
__device__ __half g_atth[4096UL * 4096];
__device__ __half g_qh  [131072UL * 128];
__device__ __half g_khT [32UL * 128 * 1024];
__device__ __half g_vh  [32UL * 1024 * 128];

struct HxStreams {
    cudaStream_t s1, s2, s3;
    cudaEvent_t e_root, e_x, e_wq, e_k, e_v, e_gate;
    HxStreams() {
        cudaStreamCreateWithFlags(&s1, cudaStreamNonBlocking);
        cudaStreamCreateWithFlags(&s2, cudaStreamNonBlocking);
        cudaStreamCreateWithFlags(&s3, cudaStreamNonBlocking);
        cudaEventCreateWithFlags(&e_root, cudaEventDisableTiming);
        cudaEventCreateWithFlags(&e_x,    cudaEventDisableTiming);
        cudaEventCreateWithFlags(&e_wq,   cudaEventDisableTiming);
        cudaEventCreateWithFlags(&e_k,    cudaEventDisableTiming);
        cudaEventCreateWithFlags(&e_v,    cudaEventDisableTiming);
        cudaEventCreateWithFlags(&e_gate, cudaEventDisableTiming);
    }
};
static HxStreams hxs;

__device__ __forceinline__ uint32_t smem_u32(const void* p) {
    uint32_t a;
    asm("{ .reg .u64 t; cvta.to.shared.u64 t, %1; cvt.u32.u64 %0, t; }"
        : "=r"(a) : "l"(p));
    return a;
}
__device__ __forceinline__ void cp16(uint32_t dst_smem, const void* src) {
    asm volatile("cp.async.cg.shared.global [%0], [%1], 16;"
                 :: "r"(dst_smem), "l"(src));
}
__device__ __forceinline__ void ldsm4(uint32_t* r, uint32_t addr) {
    asm volatile("ldmatrix.sync.aligned.m8n8.x4.shared.b16 {%0,%1,%2,%3}, [%4];"
                 : "=r"(r[0]), "=r"(r[1]), "=r"(r[2]), "=r"(r[3]) : "r"(addr));
}
__device__ __forceinline__ void ldsm4t(uint32_t* r, uint32_t addr) {
    asm volatile("ldmatrix.sync.aligned.m8n8.x4.trans.shared.b16 {%0,%1,%2,%3}, [%4];"
                 : "=r"(r[0]), "=r"(r[1]), "=r"(r[2]), "=r"(r[3]) : "r"(addr));
}
__device__ __forceinline__ void mma_f16(float* d, const uint32_t* a,
                                        uint32_t b0, uint32_t b1) {
    asm volatile(
        "mma.sync.aligned.m16n8k16.row.col.f32.f16.f16.f32 "
        "{%0,%1,%2,%3}, {%4,%5,%6,%7}, {%8,%9}, {%0,%1,%2,%3};"
        : "+f"(d[0]), "+f"(d[1]), "+f"(d[2]), "+f"(d[3])
        : "r"(a[0]), "r"(a[1]), "r"(a[2]), "r"(a[3]), "r"(b0), "r"(b1));
}
__device__ __forceinline__ uint32_t ex2_h2(float hi, float lo) {
    uint32_t h, d;
    asm("cvt.rn.f16x2.f32 %0, %1, %2;" : "=r"(h) : "f"(hi), "f"(lo));
    asm("ex2.approx.f16x2 %0, %1;" : "=r"(d) : "r"(h));
    return d;
}
__device__ __forceinline__ float ex2f(float x) {
    float r;
    asm("ex2.approx.f32 %0, %1;" : "=f"(r) : "f"(x));
    return r;
}

// ---------------------------------------------------------------------------
// fp16 mma.sync GEMM with strided-B (colmul), dense C. do_sigmoid=1 applies
// sigmoid in the epilogue. CTA 128x128, BK=64, 2 CTAs/SM, 3-stage cp.async.
// ---------------------------------------------------------------------------
#define BM 128
#define BN 128
#define BK 64
#define STAGES 3
#define A_BYTES (128 * 128)
#define B_BYTES (64 * 256)
#define STAGE_BYTES (A_BYTES + B_BYTES)
#define GEMM_SMEM (STAGES * STAGE_BYTES)

__global__ __launch_bounds__(256, 2) void h16_gemm(
    const __half* __restrict__ A, const __half* __restrict__ B,
    float* __restrict__ C, int M, int N, int K, int ldb, int colmul,
    int do_sigmoid)
{
    extern __shared__ char smem[];
    const uint32_t sbase = smem_u32(smem);
    const int tid  = threadIdx.x;
    const int wid  = tid >> 5;
    const int lane = tid & 31;
    const int g    = lane >> 2;
    const int c    = lane & 3;

    const int m0 = blockIdx.y * BM;
    const int n0 = blockIdx.x * BN;
    const int m_warp = (wid & 1) * 64;
    const int n_warp = (wid >> 1) * 32;
    const int NKT = K / BK;

    float acc[4][4][4];
#pragma unroll
    for (int i = 0; i < 4; i++)
#pragma unroll
        for (int j = 0; j < 4; j++)
#pragma unroll
            for (int r = 0; r < 4; r++) acc[i][j][r] = 0.0f;

    const int ar  = tid >> 1;
    const int ac  = tid & 1;
    const int brr = tid >> 2;
    const int bcg = tid & 3;

    const int lrow = (lane & 7) + ((lane >> 3) & 1) * 8;
    const int lkc  = lane >> 4;
    const int lxor = lane & 7;

    auto load_tile = [&](int kt) {
        const uint32_t sa = sbase + (kt % STAGES) * STAGE_BYTES;
        const uint32_t sb = sa + A_BYTES;
        const int k0 = kt * BK;
        const __half* ap = A + (size_t)(m0 + ar) * K + k0 + ac * 32;
#pragma unroll
        for (int j = 0; j < 4; j++) {
            int ch = ac * 4 + j;
            cp16(sa + ar * 128 + ((ch ^ (ar & 7)) * 16), ap + j * 8);
        }
        const __half* bp = B + (size_t)(k0 + brr) * ldb + n0 * colmul + bcg * 32;
#pragma unroll
        for (int j = 0; j < 4; j++) {
            int ch = bcg * 4 + j;
            cp16(sb + brr * 256 + ((ch ^ (brr & 7)) * 16), bp + j * 8);
        }
        asm volatile("cp.async.commit_group;" ::: "memory");
    };

#pragma unroll
    for (int s = 0; s < STAGES - 1; s++) load_tile(s);

    for (int kt = 0; kt < NKT; kt++) {
        if (kt + STAGES - 1 < NKT) {
            asm volatile("cp.async.wait_group %0;" :: "n"(STAGES - 2) : "memory");
        } else {
            asm volatile("cp.async.wait_group 0;" ::: "memory");
        }
        __syncthreads();
        if (kt + STAGES - 1 < NKT) load_tile(kt + STAGES - 1);

        const uint32_t sa = sbase + (kt % STAGES) * STAGE_BYTES;
        const uint32_t sb = sa + A_BYTES;

#pragma unroll
        for (int ks = 0; ks < BK / 16; ks++) {
            uint32_t a[4][4], b[2][4];
#pragma unroll
            for (int mt = 0; mt < 4; mt++) {
                int row = m_warp + mt * 16 + lrow;
                ldsm4(a[mt], sa + row * 128 + (((ks * 2 + lkc) ^ lxor) * 16));
            }
#pragma unroll
            for (int p = 0; p < 2; p++) {
                int krow = ks * 16 + lrow;
                int nc = (n_warp >> 3) + p * 2 + lkc;
                ldsm4t(b[p], sb + krow * 256 + ((nc ^ (krow & 7)) * 16));
            }
#pragma unroll
            for (int mt = 0; mt < 4; mt++)
#pragma unroll
                for (int p = 0; p < 2; p++) {
                    mma_f16(acc[mt][2 * p],     a[mt], b[p][0], b[p][1]);
                    mma_f16(acc[mt][2 * p + 1], a[mt], b[p][2], b[p][3]);
                }
        }
    }

    if (do_sigmoid) {
#pragma unroll
        for (int mt = 0; mt < 4; mt++)
#pragma unroll
            for (int nt = 0; nt < 4; nt++)
#pragma unroll
                for (int r = 0; r < 4; r++)
                    acc[mt][nt][r] = 1.0f / (1.0f + __expf(-acc[mt][nt][r]));
    }

#pragma unroll
    for (int mt = 0; mt < 4; mt++) {
        const int row = m0 + m_warp + mt * 16 + g;
#pragma unroll
        for (int nt = 0; nt < 4; nt++) {
            const int col = n0 + n_warp + nt * 8 + c * 2;
            *reinterpret_cast<float2*>(&C[(size_t)row * N + col]) =
                make_float2(acc[mt][nt][0], acc[mt][nt][1]);
            *reinterpret_cast<float2*>(&C[(size_t)(row + 8) * N + col]) =
                make_float2(acc[mt][nt][2], acc[mt][nt][3]);
        }
    }
}

// ---------------------------------------------------------------------------
// float -> half conversion, 64B per thread
// ---------------------------------------------------------------------------
__global__ void f2h_kernel(const float* __restrict__ in, __half* __restrict__ out)
{
    const int i = (blockIdx.x * blockDim.x + threadIdx.x) * 16;
#pragma unroll
    for (int j = 0; j < 4; j++) {
        float4 v = *reinterpret_cast<const float4*>(in + i + j * 4);
        *reinterpret_cast<__half2*>(out + i + j * 4)     = __floats2half2_rn(v.x, v.y);
        *reinterpret_cast<__half2*>(out + i + j * 4 + 2) = __floats2half2_rn(v.z, v.w);
    }
}

// ---------------------------------------------------------------------------
// RMSNorm + RoPE core
// ---------------------------------------------------------------------------
__device__ __forceinline__ float4 norm_rope_row(
    float4 x, const float* __restrict__ w, int lane, float pos)
{
    float ss = x.x*x.x + x.y*x.y + x.z*x.z + x.w*x.w;
#pragma unroll
    for (int o = 16; o; o >>= 1) ss += __shfl_xor_sync(0xffffffffu, ss, o);
    float r = rsqrtf(ss * (1.0f / 128.0f) + 1e-6f);
    float4 wv = *reinterpret_cast<const float4*>(w + 4 * lane);
    x.x *= r * (1.0f + wv.x);
    x.y *= r * (1.0f + wv.y);
    x.z *= r * (1.0f + wv.z);
    x.w *= r * (1.0f + wv.w);

    const int h0 = lane * 4;
    const int partner = (lane < 10) ? lane + 10 : ((lane < 20) ? lane - 10 : lane);
    float px = __shfl_sync(0xffffffffu, x.x, partner);
    float py = __shfl_sync(0xffffffffu, x.y, partner);
    float pz = __shfl_sync(0xffffffffu, x.z, partner);
    float pw = __shfl_sync(0xffffffffu, x.w, partner);

    if (h0 < 80) {
        const bool first = (h0 < 40);
        const float base_i = (float)(first ? h0 : h0 - 40);
        const float sgn = first ? -1.0f : 1.0f;
        float vals[4] = {x.x, x.y, x.z, x.w};
        float ps[4]   = {px, py, pz, pw};
        const float c2 = 0.49828921423310436f;    // log2(1e6)/40
#pragma unroll
        for (int j = 0; j < 4; j++) {
            float ts = exp2f((base_i + (float)j) * c2);
            float s, cc;
            sincosf(pos / ts, &s, &cc);
            vals[j] = vals[j] * cc + sgn * ps[j] * s;
        }
        x.x = vals[0]; x.y = vals[1]; x.z = vals[2]; x.w = vals[3];
    }
    return x;
}

__global__ void norm_rope_k_kernel(
    float* __restrict__ buf, const int* __restrict__ positions,
    const float* __restrict__ w)
{
    const int gw   = (blockIdx.x * blockDim.x + threadIdx.x) >> 5;
    const int lane = threadIdx.x & 31;
    const int kh = gw & 7;
    const int m  = gw >> 3;
    float* row = buf + (size_t)m * 1024 + kh * 128;
    float4 x = *reinterpret_cast<const float4*>(row + 4 * lane);
    x = norm_rope_row(x, w, lane, (float)positions[m]);
    *reinterpret_cast<float4*>(row + 4 * lane) = x;
}

__global__ void norm_rope_q_kernel(
    const float* __restrict__ q, const int* __restrict__ positions,
    const float* __restrict__ w, __half* __restrict__ qh)
{
    const int gw   = (blockIdx.x * blockDim.x + threadIdx.x) >> 5;
    const int lane = threadIdx.x & 31;
    const int n = gw & 31;
    const int m = gw >> 5;
    const float* row = q + (size_t)m * 4096 + n * 128;
    float4 x = *reinterpret_cast<const float4*>(row + 4 * lane);
    x = norm_rope_row(x, w, lane, (float)positions[m]);
    const float scale = 0.08838834764831845f * 1.4426950408889634f;
    const int b = m >> 10, t = m & 1023;
    __half2* o = reinterpret_cast<__half2*>(
        qh + ((size_t)((b * 32 + n) * 1024 + t)) * 128 + 4 * lane);
    o[0] = __floats2half2_rn(x.x * scale, x.y * scale);
    o[1] = __floats2half2_rn(x.z * scale, x.w * scale);
}

// ---------------------------------------------------------------------------
// K transpose -> half [h][s]
// ---------------------------------------------------------------------------
__global__ void transpose_k_half(const float* __restrict__ in,
                                 __half* __restrict__ out)
{
    __shared__ float tbuf[32][33];
    const int bk = blockIdx.y;
    const int b = bk >> 3, kh = bk & 7;
    const int th = (blockIdx.x & 3) * 32;
    const int ts = (blockIdx.x >> 2) * 32;
    const int x = threadIdx.x, y = threadIdx.y;
#pragma unroll
    for (int j = 0; j < 32; j += 8)
        tbuf[y + j][x] = in[(size_t)(b * 1024 + ts + y + j) * 1024 + kh * 128 + th + x];
    __syncthreads();
#pragma unroll
    for (int j = 0; j < 32; j += 8)
        out[(size_t)(bk * 128 + th + y + j) * 1024 + ts + x] =
            __float2half_rn(tbuf[x][y + j]);
}

// ---------------------------------------------------------------------------
// V reorder+convert -> half head-major
// ---------------------------------------------------------------------------
__global__ void v_reorder_half(const float* __restrict__ in,
                               __half* __restrict__ out)
{
    const int idx = (blockIdx.x * blockDim.x + threadIdx.x) * 4;
    const int h4 = idx & 1023;
    const int bs = idx >> 10;
    const int kh = h4 >> 7, h = h4 & 127;
    const int b = bs >> 10, s = bs & 1023;
    float4 v = *reinterpret_cast<const float4*>(in + idx);
    __half2* o = reinterpret_cast<__half2*>(
        out + ((size_t)((b * 8 + kh) * 1024 + s)) * 128 + h);
    o[0] = __floats2half2_rn(v.x, v.y);
    o[1] = __floats2half2_rn(v.z, v.w);
}

// ---------------------------------------------------------------------------
// Tensor-core flash attention with FUSED gating (gates = precomputed
// sigmoid, fp32). LPT order. Q staged through KV buffer 0 -> 3 CTAs/SM.
// ---------------------------------------------------------------------------
#define ATT_SMEM 65536
#define ONES_H2 0x3C003C00u

__global__ __launch_bounds__(128, 3) void attn_tc_kernel(
    const __half* __restrict__ qh, const __half* __restrict__ khT,
    const __half* __restrict__ vh, const float* __restrict__ gates,
    __half* __restrict__ outh)
{
    extern __shared__ char smem[];
    const uint32_t sbase = smem_u32(smem);
    const int tid  = threadIdx.x;
    const int wid  = tid >> 5;
    const int lane = tid & 31;
    const int g    = lane >> 2;
    const int c    = lane & 3;
    const int lrow = (lane & 7) + ((lane >> 3) & 1) * 8;
    const int lkc  = lane >> 4;

    const int qt = 15 - blockIdx.x;
    const int n  = blockIdx.y;
    const int b  = blockIdx.z;
    const int kh = n >> 2;
    const int bkh = b * 8 + kh;
    const int NT = qt + 1;

    auto load_kv = [&](int kt) {
        const uint32_t skb = sbase + (kt & 1) * 32768;
        const uint32_t svb = skb + 16384;
        const __half* kp = khT + ((size_t)bkh * 128) * 1024 + kt * 64;
#pragma unroll
        for (int j = 0; j < 8; j++) {
            int idx = tid + j * 128;
            int r = idx >> 3, ch = idx & 7;
            cp16(skb + r * 128 + ((ch ^ (r & 7)) * 16), kp + (size_t)r * 1024 + ch * 8);
        }
        const __half* vp = vh + ((size_t)(bkh * 1024 + kt * 64)) * 128;
#pragma unroll
        for (int j = 0; j < 8; j++) {
            int idx = tid + j * 128;
            int r = idx >> 4, ch = idx & 15;
            cp16(svb + r * 256 + ((ch ^ (r & 7)) * 16), vp + r * 128 + ch * 8);
        }
        asm volatile("cp.async.commit_group;" ::: "memory");
    };

    // prologue: stage Q through buffer 0, extract fragments
    {
        const __half* qp = qh + ((size_t)((b * 32 + n) * 1024 + qt * 64)) * 128;
#pragma unroll
        for (int j = 0; j < 8; j++) {
            int idx = tid + j * 128;
            int r = idx >> 4, ch = idx & 15;
            cp16(sbase + r * 256 + ((ch ^ (r & 7)) * 16), qp + r * 128 + ch * 8);
        }
        asm volatile("cp.async.commit_group;" ::: "memory");
        asm volatile("cp.async.wait_group 0;" ::: "memory");
        __syncthreads();
    }
    uint32_t qa[8][4];
#pragma unroll
    for (int ks = 0; ks < 8; ks++) {
        int row = wid * 16 + lrow;
        ldsm4(qa[ks], sbase + row * 256 + (((ks * 2 + lkc) ^ (lrow & 7)) * 16));
    }
    __syncthreads();

    load_kv(0);
    if (NT > 1) load_kv(1);

    float o[16][4];
#pragma unroll
    for (int i = 0; i < 16; i++)
#pragma unroll
        for (int r = 0; r < 4; r++) o[i][r] = 0.0f;
    float ol[4] = {0.f, 0.f, 0.f, 0.f};
    float m0 = -3.4e38f, m1 = -3.4e38f;

    for (int kt = 0; kt < NT; kt++) {
        if (kt + 1 < NT) {
            asm volatile("cp.async.wait_group 1;" ::: "memory");
        } else {
            asm volatile("cp.async.wait_group 0;" ::: "memory");
        }
        __syncthreads();

        const uint32_t skb = sbase + (kt & 1) * 32768;
        const uint32_t svb = skb + 16384;

        float sc[8][4];
#pragma unroll
        for (int i = 0; i < 8; i++)
#pragma unroll
            for (int r = 0; r < 4; r++) sc[i][r] = 0.0f;

#pragma unroll
        for (int ks = 0; ks < 8; ks++) {
            uint32_t bk[4][4];
            int krow = ks * 16 + lrow;
#pragma unroll
            for (int p = 0; p < 4; p++) {
                int nc = p * 2 + lkc;
                ldsm4t(bk[p], skb + krow * 128 + ((nc ^ (krow & 7)) * 16));
            }
#pragma unroll
            for (int p = 0; p < 4; p++) {
                mma_f16(sc[2 * p],     qa[ks], bk[p][0], bk[p][1]);
                mma_f16(sc[2 * p + 1], qa[ks], bk[p][2], bk[p][3]);
            }
        }

        const int r0 = wid * 16 + g;
        if (kt == qt) {
#pragma unroll
            for (int j = 0; j < 8; j++) {
                int k0 = j * 8 + 2 * c;
                if (k0     > r0)     sc[j][0] = -1e30f;
                if (k0 + 1 > r0)     sc[j][1] = -1e30f;
                if (k0     > r0 + 8) sc[j][2] = -1e30f;
                if (k0 + 1 > r0 + 8) sc[j][3] = -1e30f;
            }
        }

        float mx0 = -3.4e38f, mx1 = -3.4e38f;
#pragma unroll
        for (int j = 0; j < 8; j++) {
            mx0 = fmaxf(mx0, fmaxf(sc[j][0], sc[j][1]));
            mx1 = fmaxf(mx1, fmaxf(sc[j][2], sc[j][3]));
        }
        mx0 = fmaxf(mx0, __shfl_xor_sync(0xffffffffu, mx0, 1));
        mx0 = fmaxf(mx0, __shfl_xor_sync(0xffffffffu, mx0, 2));
        mx1 = fmaxf(mx1, __shfl_xor_sync(0xffffffffu, mx1, 1));
        mx1 = fmaxf(mx1, __shfl_xor_sync(0xffffffffu, mx1, 2));

        float mn0 = fmaxf(m0, mx0), mn1 = fmaxf(m1, mx1);
        float a0 = ex2f(m0 - mn0), a1 = ex2f(m1 - mn1);
        m0 = mn0; m1 = mn1;

        uint32_t p_lo[8], p_hi[8];
#pragma unroll
        for (int j = 0; j < 8; j++) {
            p_lo[j] = ex2_h2(sc[j][1] - mn0, sc[j][0] - mn0);
            p_hi[j] = ex2_h2(sc[j][3] - mn1, sc[j][2] - mn1);
        }

        ol[0] *= a0; ol[1] *= a0; ol[2] *= a1; ol[3] *= a1;
#pragma unroll
        for (int i = 0; i < 16; i++) {
            o[i][0] *= a0; o[i][1] *= a0;
            o[i][2] *= a1; o[i][3] *= a1;
        }

#pragma unroll
        for (int j2 = 0; j2 < 4; j2++) {
            uint32_t pa[4] = { p_lo[2 * j2], p_hi[2 * j2],
                               p_lo[2 * j2 + 1], p_hi[2 * j2 + 1] };
            mma_f16(ol, pa, ONES_H2, ONES_H2);
            int krow = j2 * 16 + lrow;
#pragma unroll
            for (int p = 0; p < 8; p++) {
                uint32_t bv[4];
                int nc = p * 2 + lkc;
                ldsm4t(bv, svb + krow * 256 + ((nc ^ (krow & 7)) * 16));
                mma_f16(o[2 * p],     pa, bv[0], bv[1]);
                mma_f16(o[2 * p + 1], pa, bv[2], bv[3]);
            }
        }

        __syncthreads();
        if (kt + 2 < NT) load_kv(kt + 2);
    }

    // epilogue: 1/l and gate multiply fused
    const float inv0 = 1.0f / ol[0], inv1 = 1.0f / ol[2];
    const int tq0 = qt * 64 + wid * 16 + g;
    const int tq1 = tq0 + 8;
    const float* gp0 = gates + (size_t)(b * 1024 + tq0) * 4096 + n * 128;
    const float* gp1 = gates + (size_t)(b * 1024 + tq1) * 4096 + n * 128;
    __half* out0 = outh + (size_t)(b * 1024 + tq0) * 4096 + n * 128;
    __half* out1 = outh + (size_t)(b * 1024 + tq1) * 4096 + n * 128;
#pragma unroll
    for (int p = 0; p < 16; p++) {
        int col = p * 8 + 2 * c;
        float2 gv0 = *reinterpret_cast<const float2*>(gp0 + col);
        float2 gv1 = *reinterpret_cast<const float2*>(gp1 + col);
        *reinterpret_cast<__half2*>(out0 + col) =
            __floats2half2_rn(o[p][0] * inv0 * gv0.x, o[p][1] * inv0 * gv0.y);
        *reinterpret_cast<__half2*>(out1 + col) =
            __floats2half2_rn(o[p][2] * inv1 * gv1.x, o[p][3] * inv1 * gv1.y);
    }
}

// ---------------------------------------------------------------------------
// Launcher: gating fused into attention epilogue; gate_apply deleted.
// ---------------------------------------------------------------------------
extern "C" void kernel_launch(void* const* d_in, const int* in_sizes, int n_in,
                              void* d_out, int out_size)
{
    const float* x   = (const float*)d_in[0];
    const int*   pos = (const int*)  d_in[1];
    const float* wq  = (const float*)d_in[2];
    const float* wk  = (const float*)d_in[3];
    const float* wv  = (const float*)d_in[4];
    const float* wo  = (const float*)d_in[5];
    const float* qw  = (const float*)d_in[6];
    const float* kw  = (const float*)d_in[7];
    float* out = (float*)d_out;

    float  *qb, *gateb, *kb, *vb;
    __half *xh, *wqh, *wkh, *wvh, *woh, *atth, *qh, *khT, *vh;
    cudaGetSymbolAddress((void**)&qb,    g_q);
    cudaGetSymbolAddress((void**)&gateb, g_gate);
    cudaGetSymbolAddress((void**)&kb,    g_k);
    cudaGetSymbolAddress((void**)&vb,    g_v);
    cudaGetSymbolAddress((void**)&xh,    g_xh);
    cudaGetSymbolAddress((void**)&wqh,   g_wqh);
    cudaGetSymbolAddress((void**)&wkh,   g_wkh);
    cudaGetSymbolAddress((void**)&wvh,   g_wvh);
    cudaGetSymbolAddress((void**)&woh,   g_woh);
    cudaGetSymbolAddress((void**)&atth,  g_atth);
    cudaGetSymbolAddress((void**)&qh,    g_qh);
    cudaGetSymbolAddress((void**)&khT,   g_khT);
    cudaGetSymbolAddress((void**)&vh,    g_vh);

    static bool attr_set = false;
    if (!attr_set) {
        cudaFuncSetAttribute(h16_gemm, cudaFuncAttributeMaxDynamicSharedMemorySize,
                             GEMM_SMEM);
        cudaFuncSetAttribute(attn_tc_kernel,
                             cudaFuncAttributeMaxDynamicSharedMemorySize, ATT_SMEM);
        attr_set = true;
    }

    cudaStream_t s0 = 0;

    cudaEventRecord(hxs.e_root, s0);
    cudaStreamWaitEvent(hxs.s1, hxs.e_root, 0);
    cudaStreamWaitEvent(hxs.s2, hxs.e_root, 0);
    cudaStreamWaitEvent(hxs.s3, hxs.e_root, 0);

    // main: x conversion
    f2h_kernel<<<(4096UL * 4096) / 4096, 256, 0, s0>>>(x, xh);
    cudaEventRecord(hxs.e_x, s0);

    // s3: wq conversion at root (parallel with x), then wo conversion
    f2h_kernel<<<(4096UL * 8192) / 4096, 256, 0, hxs.s3>>>(wq, wqh);
    cudaEventRecord(hxs.e_wq, hxs.s3);
    f2h_kernel<<<(4096UL * 4096) / 4096, 256, 0, hxs.s3>>>(wo, woh);

    // s1: K chain
    f2h_kernel<<<(4096UL * 1024) / 4096, 256, 0, hxs.s1>>>(wk, wkh);
    cudaStreamWaitEvent(hxs.s1, hxs.e_x, 0);
    h16_gemm<<<dim3(8, 32), 256, GEMM_SMEM, hxs.s1>>>(
        xh, wkh, kb, 4096, 1024, 4096, 1024, 1, 0);
    norm_rope_k_kernel<<<(4096 * 8) / 8, 256, 0, hxs.s1>>>(kb, pos, kw);
    transpose_k_half<<<dim3(128, 32), dim3(32, 8), 0, hxs.s1>>>(kb, khT);
    cudaEventRecord(hxs.e_k, hxs.s1);

    // s2: V chain
    f2h_kernel<<<(4096UL * 1024) / 4096, 256, 0, hxs.s2>>>(wv, wvh);
    cudaStreamWaitEvent(hxs.s2, hxs.e_x, 0);
    h16_gemm<<<dim3(8, 32), 256, GEMM_SMEM, hxs.s2>>>(
        xh, wvh, vb, 4096, 1024, 4096, 1024, 1, 0);
    v_reorder_half<<<(4096UL * 1024) / 1024, 256, 0, hxs.s2>>>(vb, vh);
    cudaEventRecord(hxs.e_v, hxs.s2);

    // main: q-GEMM (waits wq conversion), norm
    cudaStreamWaitEvent(s0, hxs.e_wq, 0);
    h16_gemm<<<dim3(32, 32), 256, GEMM_SMEM, s0>>>(
        xh, wqh, qb, 4096, 4096, 4096, 8192, 2, 0);
    norm_rope_q_kernel<<<(4096 * 32) / 8, 256, 0, s0>>>(qb, pos, qw, qh);

    // s3: gate-GEMM with fused sigmoid
    cudaStreamWaitEvent(hxs.s3, hxs.e_x, 0);
    h16_gemm<<<dim3(32, 32), 256, GEMM_SMEM, hxs.s3>>>(
        xh, wqh + 128, gateb, 4096, 4096, 4096, 8192, 2, 1);
    cudaEventRecord(hxs.e_gate, hxs.s3);

    // main: join K/V + gates, attention with fused gating
    cudaStreamWaitEvent(s0, hxs.e_k, 0);
    cudaStreamWaitEvent(s0, hxs.e_v, 0);
    cudaStreamWaitEvent(s0, hxs.e_gate, 0);
    attn_tc_kernel<<<dim3(16, 32, 4), 128, ATT_SMEM, s0>>>(qh, khT, vh, gateb, atth);

    // out-projection (woh ordered via e_gate on s3)
    h16_gemm<<<dim3(32, 32), 256, GEMM_SMEM, s0>>>(
        atth, woh, out, 4096, 4096, 4096, 4096, 1, 0);
}